// round 11
// baseline (speedup 1.0000x reference)
#include <cuda_runtime.h>
#include <cuda_fp16.h>
#include <cstdint>

#define DEV_INLINE __device__ __forceinline__

// Problem constants
constexpr int B_    = 16;
constexpr int N_    = 1024;
constexpr int H_    = 16;
constexpr int D_    = 128;
constexpr int DIM_  = 2048;
constexpr int QKV_OUT_ = 6144;
constexpr int ROWS_ = B_ * N_;     // 16384
constexpr int BH_   = B_ * H_;     // 256
constexpr float SCALE_ = 0.08838834764831845f;  // 128^-0.5
constexpr float LN_EPS_ = 1e-5f;

// ---------------- device scratch (static, no allocs) ----------------
__device__ __align__(16) __half g_xn  [(size_t)ROWS_ * DIM_];
__device__ __align__(16) __half g_wqkv[(size_t)DIM_ * QKV_OUT_];
__device__ __align__(16) __half g_wproj[(size_t)DIM_ * DIM_];
__device__ __align__(16) __half g_q   [(size_t)BH_ * N_ * D_];       // [bh][n][d], pre-scaled
__device__ __align__(16) __half g_k   [(size_t)BH_ * N_ * D_];       // [bh][n][d]
__device__ __align__(16) __half g_v   [(size_t)BH_ * N_ * D_];       // [bh][n][d]
__device__ __align__(16) __half g_bias16[(size_t)H_ * N_ * N_];      // gathered bias fp16
__device__ __align__(16) __half g_ao  [(size_t)ROWS_ * DIM_];        // attn out [b,n,h*D+d]

// ---------------- helpers ----------------
DEV_INLINE uint32_t smem_u32(const void* p) {
    return (uint32_t)__cvta_generic_to_shared(p);
}
DEV_INLINE void cp16(void* s, const void* g) {
    asm volatile("cp.async.cg.shared.global [%0], [%1], 16;\n"
                 :: "r"(smem_u32(s)), "l"(g));
}
DEV_INLINE void cp_commit() { asm volatile("cp.async.commit_group;\n"); }
template <int n>
DEV_INLINE void cp_wait() { asm volatile("cp.async.wait_group %0;\n" :: "n"(n)); }

DEV_INLINE uint32_t h2_as_u32(__half2 h) {
    return *reinterpret_cast<uint32_t*>(&h);
}

DEV_INLINE void ldsm_x4(uint32_t& r0, uint32_t& r1, uint32_t& r2, uint32_t& r3, uint32_t a) {
    asm volatile("ldmatrix.sync.aligned.m8n8.x4.shared.b16 {%0,%1,%2,%3}, [%4];"
                 : "=r"(r0), "=r"(r1), "=r"(r2), "=r"(r3) : "r"(a));
}
DEV_INLINE void ldsm_x4_t(uint32_t& r0, uint32_t& r1, uint32_t& r2, uint32_t& r3, uint32_t a) {
    asm volatile("ldmatrix.sync.aligned.m8n8.x4.trans.shared.b16 {%0,%1,%2,%3}, [%4];"
                 : "=r"(r0), "=r"(r1), "=r"(r2), "=r"(r3) : "r"(a));
}
DEV_INLINE void mma16816(float* c, const uint32_t* a, const uint32_t* b) {
    asm volatile(
        "mma.sync.aligned.m16n8k16.row.col.f32.f16.f16.f32 "
        "{%0,%1,%2,%3}, {%4,%5,%6,%7}, {%8,%9}, {%0,%1,%2,%3};"
        : "+f"(c[0]), "+f"(c[1]), "+f"(c[2]), "+f"(c[3])
        : "r"(a[0]), "r"(a[1]), "r"(a[2]), "r"(a[3]), "r"(b[0]), "r"(b[1]));
}

DEV_INLINE float warp_sum(float v) {
    #pragma unroll
    for (int o = 16; o; o >>= 1) v += __shfl_xor_sync(0xFFFFFFFFu, v, o);
    return v;
}
DEV_INLINE float block_sum(float v, float* sred, int tid) {
    int lane = tid & 31, w = tid >> 5;
    v = warp_sum(v);
    if (lane == 0) sred[w] = v;
    __syncthreads();
    float r = sred[0];
    #pragma unroll
    for (int i = 1; i < 8; i++) r += sred[i];
    __syncthreads();
    return r;
}

// ---------------- weight fp32 -> fp16 conversion ----------------
__global__ void cvt_kernel(const float4* __restrict__ qkv_w, const float4* __restrict__ proj_w) {
    int i = blockIdx.x * blockDim.x + threadIdx.x;
    const int n1 = DIM_ * QKV_OUT_ / 4;
    const int n2 = DIM_ * DIM_ / 4;
    if (i < n1) {
        float4 v = qkv_w[i];
        __half2* dst = (__half2*)g_wqkv;
        dst[2 * i]     = __floats2half2_rn(v.x, v.y);
        dst[2 * i + 1] = __floats2half2_rn(v.z, v.w);
    } else if (i < n1 + n2) {
        int j = i - n1;
        float4 v = proj_w[j];
        __half2* dst = (__half2*)g_wproj;
        dst[2 * j]     = __floats2half2_rn(v.x, v.y);
        dst[2 * j + 1] = __floats2half2_rn(v.z, v.w);
    }
}

// ---------------- gather attention bias to fp16 [h][i][j] ----------------
__global__ void bias16_kernel(const float* __restrict__ att_bias,
                              const int* __restrict__ idxs, int n_off) {
    int ij = blockIdx.x * 256 + threadIdx.x;
    int h  = blockIdx.y;
    g_bias16[(size_t)h * N_ * N_ + ij] =
        __float2half(att_bias[h * n_off + idxs[ij]]);
}

// ---------------- LayerNorm ----------------
__global__ void ln_kernel(const float* __restrict__ x,
                          const float* __restrict__ gamma,
                          const float* __restrict__ beta) {
    __shared__ float sred[8];
    int row = blockIdx.x;
    int tid = threadIdx.x;
    const float4* x4 = (const float4*)(x + (size_t)row * DIM_);
    float4 v0 = x4[tid];
    float4 v1 = x4[tid + 256];

    float s = v0.x + v0.y + v0.z + v0.w + v1.x + v1.y + v1.z + v1.w;
    float q = v0.x*v0.x + v0.y*v0.y + v0.z*v0.z + v0.w*v0.w
            + v1.x*v1.x + v1.y*v1.y + v1.z*v1.z + v1.w*v1.w;

    float tot_s = block_sum(s, sred, tid);
    float tot_q = block_sum(q, sred, tid);
    float mean = tot_s * (1.0f / DIM_);
    float var  = tot_q * (1.0f / DIM_) - mean * mean;
    float rstd = rsqrtf(var + LN_EPS_);

    const float4* g4 = (const float4*)gamma;
    const float4* b4 = (const float4*)beta;
    float4 ga = g4[tid], gb = g4[tid + 256];
    float4 ba = b4[tid], bb = b4[tid + 256];

    __half2* o2 = (__half2*)(g_xn + (size_t)row * DIM_);
    o2[2 * tid]       = __floats2half2_rn((v0.x - mean) * rstd * ga.x + ba.x,
                                          (v0.y - mean) * rstd * ga.y + ba.y);
    o2[2 * tid + 1]   = __floats2half2_rn((v0.z - mean) * rstd * ga.z + ba.z,
                                          (v0.w - mean) * rstd * ga.w + ba.w);
    o2[512 + 2 * tid]     = __floats2half2_rn((v1.x - mean) * rstd * gb.x + bb.x,
                                              (v1.y - mean) * rstd * gb.y + bb.y);
    o2[512 + 2 * tid + 1] = __floats2half2_rn((v1.z - mean) * rstd * gb.z + bb.z,
                                              (v1.w - mean) * rstd * gb.w + bb.w);
}

// ------- dense GEMMs (QKV / proj): 4-stage cp.async, ONE barrier/iter (R7) -------
enum { EPI_QKV = 0, EPI_PROJ = 1 };

constexpr int AS_STAGE_B = 128 * 40 * 2;   // 10240
constexpr int BS_STAGE_B = 32 * 136 * 2;   //  8704
constexpr int AS_TOT_B   = 4 * AS_STAGE_B; // 40960
constexpr int GEMM_SMEM  = AS_TOT_B + 4 * BS_STAGE_B;  // 75776

template <int EPI>
__global__ void __launch_bounds__(256, 2)
gemm_f16(const float* __restrict__ bias, float* __restrict__ outf) {
    constexpr int K   = 2048;
    constexpr int LDA = 2048;
    constexpr int LDB = (EPI == EPI_QKV) ? 6144 : 2048;
    constexpr int NT  = K / 32;   // 64 k-tiles

    extern __shared__ __align__(16) char dynsm[];

    const int bm = blockIdx.y * 128;
    const int bn = blockIdx.x * 128;

    const __half* __restrict__ A  = (EPI == EPI_QKV) ? g_xn : g_ao;
    const __half* __restrict__ Bp = (EPI == EPI_QKV) ? g_wqkv : g_wproj;

    const int tid  = threadIdx.x;
    const int lane = tid & 31;
    const int warp = tid >> 5;
    const int wm = warp & 3;
    const int wn = warp >> 2;

    float acc[2][8][4];
    #pragma unroll
    for (int i = 0; i < 2; i++)
        #pragma unroll
        for (int j = 0; j < 8; j++)
            #pragma unroll
            for (int r = 0; r < 4; r++) acc[i][j][r] = 0.0f;

    auto As = [&](int s) -> __half (*)[40] {
        return reinterpret_cast<__half(*)[40]>(dynsm + s * AS_STAGE_B);
    };
    auto Bs = [&](int s) -> __half (*)[136] {
        return reinterpret_cast<__half(*)[136]>(dynsm + AS_TOT_B + s * BS_STAGE_B);
    };

    auto load_tile = [&](int s, int k0) {
        __half (*as)[40]  = As(s);
        __half (*bs)[136] = Bs(s);
        #pragma unroll
        for (int i = 0; i < 2; i++) {
            int lin = tid + i * 256;
            int m  = lin >> 2;
            int kq = (lin & 3) << 3;
            cp16(&as[m][kq], &A[(size_t)(bm + m) * LDA + k0 + kq]);
        }
        #pragma unroll
        for (int i = 0; i < 2; i++) {
            int lin = tid + i * 256;
            int kk = lin >> 4;
            int cq = (lin & 15) << 3;
            cp16(&bs[kk][cq], &Bp[(size_t)(k0 + kk) * LDB + bn + cq]);
        }
        cp_commit();
    };

    load_tile(0, 0);
    load_tile(1, 32);
    load_tile(2, 64);

    #pragma unroll 1
    for (int t = 0; t < NT; t++) {
        if (t <= NT - 3)      cp_wait<2>();
        else if (t == NT - 2) cp_wait<1>();
        else                  cp_wait<0>();
        __syncthreads();   // single barrier per iteration

        if (t + 3 < NT) load_tile((t + 3) & 3, (t + 3) * 32);

        const int s = t & 3;
        __half (*as)[40]  = As(s);
        __half (*bs)[136] = Bs(s);
        #pragma unroll
        for (int ks = 0; ks < 2; ks++) {
            uint32_t af[2][4];
            #pragma unroll
            for (int mf = 0; mf < 2; mf++) {
                uint32_t addr = smem_u32(
                    &as[wm * 32 + mf * 16 + (lane & 15)][ks * 16 + ((lane >> 4) << 3)]);
                ldsm_x4(af[mf][0], af[mf][1], af[mf][2], af[mf][3], addr);
            }
            uint32_t bf[8][2];
            #pragma unroll
            for (int np = 0; np < 4; np++) {
                uint32_t addr = smem_u32(
                    &bs[ks * 16 + (lane & 15)][wn * 64 + np * 16 + ((lane >> 4) << 3)]);
                uint32_t r0, r1, r2, r3;
                ldsm_x4_t(r0, r1, r2, r3, addr);
                bf[np * 2][0] = r0;     bf[np * 2][1] = r1;
                bf[np * 2 + 1][0] = r2; bf[np * 2 + 1][1] = r3;
            }
            #pragma unroll
            for (int mf = 0; mf < 2; mf++)
                #pragma unroll
                for (int nf = 0; nf < 8; nf++)
                    mma16816(acc[mf][nf], af[mf], bf[nf]);
        }
    }

    // epilogue
    const int g     = lane >> 2;
    const int cpair = (lane & 3) << 1;
    #pragma unroll
    for (int mf = 0; mf < 2; mf++)
        #pragma unroll
        for (int nf = 0; nf < 8; nf++) {
            int row0 = bm + wm * 32 + mf * 16 + g;
            int col  = bn + wn * 64 + nf * 8 + cpair;
            #pragma unroll
            for (int rr = 0; rr < 2; rr++) {
                int row = row0 + rr * 8;
                float v0 = acc[mf][nf][rr * 2];
                float v1 = acc[mf][nf][rr * 2 + 1];
                if constexpr (EPI == EPI_QKV) {
                    v0 += bias[col];
                    v1 += bias[col + 1];
                    int tsel = col >> 11;
                    int r = col & 2047;
                    int h = r >> 7, d = r & 127;
                    int b = row >> 10, n = row & 1023;
                    int bhi = (b << 4) + h;
                    size_t off = ((size_t)bhi * N_ + n) * D_ + d;
                    if (tsel == 0) {
                        *(__half2*)&g_q[off] = __floats2half2_rn(v0 * SCALE_, v1 * SCALE_);
                    } else if (tsel == 1) {
                        *(__half2*)&g_k[off] = __floats2half2_rn(v0, v1);
                    } else {
                        *(__half2*)&g_v[off] = __floats2half2_rn(v0, v1);
                    }
                } else {
                    float2 o;
                    o.x = v0 + bias[col];
                    o.y = v1 + bias[col + 1];
                    *(float2*)&outf[(size_t)row * DIM_ + col] = o;
                }
            }
        }
}

// ---- fused flash attention: 64-row KV tiles, 2 CTAs/SM, K/V/bias in smem ----
constexpr int FL_KV      = 64;                        // kv rows per tile
constexpr int FL_NJT     = N_ / FL_KV;                // 16 iterations
constexpr int FL_STRIDE  = 136;                       // K/V row stride (halves)
constexpr int FL_BSTRIDE = 72;                        // bias row stride (halves)
constexpr int FL_KVT     = FL_KV * FL_STRIDE;         // K or V tile (halves) 8704
constexpr int FL_BT      = 128 * FL_BSTRIDE;          // bias tile (halves)   9216
constexpr int FL_STAGE   = 2 * FL_KVT + FL_BT;        // 26624 halves
constexpr int FL_SMEM_BYTES = 2 * FL_STAGE * 2;       // 106496 bytes -> 2 CTAs/SM

__global__ void __launch_bounds__(256, 2)
flash_kernel() {
    extern __shared__ char g_smem[];
    __half* sm = (__half*)g_smem;

    const int tid  = threadIdx.x;
    const int lane = tid & 31;
    const int w    = tid >> 5;
    const int qt   = blockIdx.x;
    const int bh   = blockIdx.y;
    const int h    = bh & 15;
    const int b    = bh >> 4;

    const __half* __restrict__ Qp = g_q + ((size_t)bh * N_ + qt * 128) * D_;
    const __half* __restrict__ Kp = g_k + (size_t)bh * N_ * D_;
    const __half* __restrict__ Vp = g_v + (size_t)bh * N_ * D_;
    const __half* __restrict__ Bb = g_bias16 + (size_t)h * N_ * N_ + (size_t)(qt * 128) * N_;

    // ---- stage Q through smem (stage-0 area, 34.8KB < 53.2KB), get fragments ----
    {
        __half* sQ = sm;
        #pragma unroll
        for (int i = 0; i < 8; i++) {
            int chunk = tid + i * 256;
            int r  = chunk >> 4;
            int c8 = (chunk & 15) << 3;
            *(float4*)&sQ[r * FL_STRIDE + c8] = *(const float4*)&Qp[r * D_ + c8];
        }
    }
    __syncthreads();
    uint32_t aq[8][4];
    #pragma unroll
    for (int kc = 0; kc < 8; kc++) {
        uint32_t addr = smem_u32(
            &sm[(w * 16 + (lane & 15)) * FL_STRIDE + kc * 16 + ((lane >> 4) << 3)]);
        ldsm_x4(aq[kc][0], aq[kc][1], aq[kc][2], aq[kc][3], addr);
    }
    __syncthreads();

    auto load_kv = [&](int s, int jt) {
        __half* sK = sm + s * FL_STAGE;
        __half* sV = sK + FL_KVT;
        __half* sB = sV + FL_KVT;
        #pragma unroll
        for (int i = 0; i < 4; i++) {               // K: 64 x 128
            int chunk = tid + i * 256;
            int r  = chunk >> 4;
            int c8 = (chunk & 15) << 3;
            cp16(&sK[r * FL_STRIDE + c8], &Kp[(size_t)(jt * FL_KV + r) * D_ + c8]);
        }
        #pragma unroll
        for (int i = 0; i < 4; i++) {               // V: 64 x 128
            int chunk = tid + i * 256;
            int r  = chunk >> 4;
            int c8 = (chunk & 15) << 3;
            cp16(&sV[r * FL_STRIDE + c8], &Vp[(size_t)(jt * FL_KV + r) * D_ + c8]);
        }
        #pragma unroll
        for (int i = 0; i < 4; i++) {               // bias: 128 q-rows x 64 cols
            int chunk = tid + i * 256;               // 1024 chunks of 8 halves
            int r  = chunk >> 3;                     // 0..127
            int c8 = (chunk & 7) << 3;               // 0..56
            cp16(&sB[r * FL_BSTRIDE + c8], &Bb[(size_t)r * N_ + jt * FL_KV + c8]);
        }
        cp_commit();
    };

    float acc_o[16][4];
    #pragma unroll
    for (int i = 0; i < 16; i++)
        #pragma unroll
        for (int r = 0; r < 4; r++) acc_o[i][r] = 0.0f;
    float m0 = -1e30f, m1 = -1e30f, l0 = 0.0f, l1 = 0.0f;

    const int g = lane >> 2;

    load_kv(0, 0);

    #pragma unroll 1
    for (int jt = 0; jt < FL_NJT; jt++) {
        if (jt + 1 < FL_NJT) { load_kv((jt + 1) & 1, jt + 1); cp_wait<1>(); }
        else                 { cp_wait<0>(); }
        __syncthreads();

        const __half* sK = sm + (jt & 1) * FL_STAGE;
        const __half* sV = sK + FL_KVT;
        const __half* sB = sV + FL_KVT;

        // ---- S = Q K^T (16 x 64 per warp) ----
        float accs[8][4];
        #pragma unroll
        for (int i = 0; i < 8; i++)
            #pragma unroll
            for (int r = 0; r < 4; r++) accs[i][r] = 0.0f;

        #pragma unroll
        for (int kc = 0; kc < 8; kc++) {
            #pragma unroll
            for (int nf2 = 0; nf2 < 4; nf2++) {
                uint32_t r0, r1, r2, r3;
                uint32_t addr = smem_u32(
                    &sK[(nf2 * 16 + (lane & 15)) * FL_STRIDE + kc * 16 + ((lane >> 4) << 3)]);
                ldsm_x4(r0, r1, r2, r3, addr);
                uint32_t bA[2] = {r0, r2}, bB[2] = {r1, r3};
                mma16816(accs[nf2 * 2],     aq[kc], bA);
                mma16816(accs[nf2 * 2 + 1], aq[kc], bB);
            }
        }

        // ---- bias add (from smem) + online softmax over 64 cols ----
        const int cpair = (lane & 3) << 1;
        const __half* srow0 = sB + (size_t)(w * 16 + g) * FL_BSTRIDE;
        const __half* srow1 = srow0 + 8 * FL_BSTRIDE;
        float mx0 = -1e30f, mx1 = -1e30f;
        #pragma unroll
        for (int nf = 0; nf < 8; nf++) {
            int col = nf * 8 + cpair;
            __half2 b0 = *(const __half2*)&srow0[col];
            __half2 b1 = *(const __half2*)&srow1[col];
            accs[nf][0] += __low2float(b0);
            accs[nf][1] += __high2float(b0);
            accs[nf][2] += __low2float(b1);
            accs[nf][3] += __high2float(b1);
            mx0 = fmaxf(mx0, fmaxf(accs[nf][0], accs[nf][1]));
            mx1 = fmaxf(mx1, fmaxf(accs[nf][2], accs[nf][3]));
        }
        mx0 = fmaxf(mx0, __shfl_xor_sync(0xFFFFFFFFu, mx0, 1));
        mx0 = fmaxf(mx0, __shfl_xor_sync(0xFFFFFFFFu, mx0, 2));
        mx1 = fmaxf(mx1, __shfl_xor_sync(0xFFFFFFFFu, mx1, 1));
        mx1 = fmaxf(mx1, __shfl_xor_sync(0xFFFFFFFFu, mx1, 2));

        float mn0 = fmaxf(m0, mx0), mn1 = fmaxf(m1, mx1);
        float sc0 = __expf(m0 - mn0), sc1 = __expf(m1 - mn1);
        m0 = mn0; m1 = mn1;

        float sum0 = 0.0f, sum1 = 0.0f;
        uint32_t ph[4][4];
        #pragma unroll
        for (int nf = 0; nf < 8; nf++) {
            float p0 = __expf(accs[nf][0] - m0);
            float p1 = __expf(accs[nf][1] - m0);
            float p2 = __expf(accs[nf][2] - m1);
            float p3 = __expf(accs[nf][3] - m1);
            sum0 += p0 + p1;
            sum1 += p2 + p3;
            uint32_t lo = h2_as_u32(__floats2half2_rn(p0, p1));
            uint32_t hi = h2_as_u32(__floats2half2_rn(p2, p3));
            int kc = nf >> 1;
            if ((nf & 1) == 0) { ph[kc][0] = lo; ph[kc][1] = hi; }
            else               { ph[kc][2] = lo; ph[kc][3] = hi; }
        }
        sum0 += __shfl_xor_sync(0xFFFFFFFFu, sum0, 1);
        sum0 += __shfl_xor_sync(0xFFFFFFFFu, sum0, 2);
        sum1 += __shfl_xor_sync(0xFFFFFFFFu, sum1, 1);
        sum1 += __shfl_xor_sync(0xFFFFFFFFu, sum1, 2);
        l0 = l0 * sc0 + sum0;
        l1 = l1 * sc1 + sum1;

        #pragma unroll
        for (int nf = 0; nf < 16; nf++) {
            acc_o[nf][0] *= sc0; acc_o[nf][1] *= sc0;
            acc_o[nf][2] *= sc1; acc_o[nf][3] *= sc1;
        }

        // ---- O += P V  (P: 16 x 64, V: 64 x 128) ----
        #pragma unroll
        for (int kc = 0; kc < 4; kc++) {
            #pragma unroll
            for (int nf2 = 0; nf2 < 8; nf2++) {
                uint32_t r0, r1, r2, r3;
                uint32_t addr = smem_u32(
                    &sV[(kc * 16 + (lane & 15)) * FL_STRIDE + nf2 * 16 + ((lane >> 4) << 3)]);
                ldsm_x4_t(r0, r1, r2, r3, addr);
                uint32_t bA[2] = {r0, r1}, bB[2] = {r2, r3};
                mma16816(acc_o[nf2 * 2],     ph[kc], bA);
                mma16816(acc_o[nf2 * 2 + 1], ph[kc], bB);
            }
        }
        __syncthreads();
    }

    // ---- normalize + write [b, n, h*128+d] ----
    float inv0 = __frcp_rn(l0), inv1 = __frcp_rn(l1);
    const int cpair = (lane & 3) << 1;
    int n0 = qt * 128 + w * 16 + g;
    __half* dst0 = g_ao + ((size_t)(b * N_ + n0)) * DIM_ + h * D_;
    __half* dst1 = dst0 + (size_t)8 * DIM_;
    #pragma unroll
    for (int nf = 0; nf < 16; nf++) {
        int col = nf * 8 + cpair;
        *(__half2*)&dst0[col] = __floats2half2_rn(acc_o[nf][0] * inv0, acc_o[nf][1] * inv0);
        *(__half2*)&dst1[col] = __floats2half2_rn(acc_o[nf][2] * inv1, acc_o[nf][3] * inv1);
    }
}

// ---------------- launch ----------------
extern "C" void kernel_launch(void* const* d_in, const int* in_sizes, int n_in,
                              void* d_out, int out_size) {
    const float* x        = (const float*)d_in[0];
    const float* ln_g     = (const float*)d_in[1];
    const float* ln_b     = (const float*)d_in[2];
    const float* qkv_w    = (const float*)d_in[3];
    const float* qkv_b    = (const float*)d_in[4];
    const float* proj_w   = (const float*)d_in[5];
    const float* proj_b   = (const float*)d_in[6];
    const float* att_bias = (const float*)d_in[7];
    const int*   bias_idx = (const int*)d_in[8];
    float* out = (float*)d_out;

    int n_off = in_sizes[7] / H_;   // 1024

    cudaFuncSetAttribute(flash_kernel,
                         cudaFuncAttributeMaxDynamicSharedMemorySize, FL_SMEM_BYTES);
    cudaFuncSetAttribute(gemm_f16<EPI_QKV>,
                         cudaFuncAttributeMaxDynamicSharedMemorySize, GEMM_SMEM);
    cudaFuncSetAttribute(gemm_f16<EPI_PROJ>,
                         cudaFuncAttributeMaxDynamicSharedMemorySize, GEMM_SMEM);

    // 1. weights -> fp16
    cvt_kernel<<<16384, 256>>>((const float4*)qkv_w, (const float4*)proj_w);
    // 2. LayerNorm -> fp16
    ln_kernel<<<ROWS_, 256>>>(x, ln_g, ln_b);
    // 3. gather bias -> fp16 [h][i][j]
    bias16_kernel<<<dim3(N_ * N_ / 256, H_), 256>>>(att_bias, bias_idx, n_off);
    // 4. QKV GEMM -> q(scaled)/k/v [bh][n][d]
    gemm_f16<EPI_QKV><<<dim3(QKV_OUT_ / 128, ROWS_ / 128), 256, GEMM_SMEM>>>(
        qkv_b, nullptr);
    // 5. fused attention
    flash_kernel<<<dim3(N_ / 128, BH_), 256, FL_SMEM_BYTES>>>();
    // 6. out = AO @ proj_w + proj_b
    gemm_f16<EPI_PROJ><<<dim3(DIM_ / 128, ROWS_ / 128), 256, GEMM_SMEM>>>(
        proj_b, out);
}

// round 12
// speedup vs baseline: 1.0423x; 1.0423x over previous
#include <cuda_runtime.h>
#include <cuda_fp16.h>
#include <cstdint>

#define DEV_INLINE __device__ __forceinline__

// Problem constants
constexpr int B_    = 16;
constexpr int N_    = 1024;
constexpr int H_    = 16;
constexpr int D_    = 128;
constexpr int DIM_  = 2048;
constexpr int QKV_OUT_ = 6144;
constexpr int ROWS_ = B_ * N_;     // 16384
constexpr int BH_   = B_ * H_;     // 256
constexpr float LOG2E_ = 1.4426950408889634f;
constexpr float SCALE_ = 0.08838834764831845f;          // 128^-0.5
constexpr float QSC_   = SCALE_ * LOG2E_;               // q pre-scale, log2 domain
constexpr float LN_EPS_ = 1e-5f;

// ---------------- device scratch (static, no allocs) ----------------
__device__ __align__(16) __half g_xn  [(size_t)ROWS_ * DIM_];
__device__ __align__(16) __half g_wqkv[(size_t)DIM_ * QKV_OUT_];
__device__ __align__(16) __half g_wproj[(size_t)DIM_ * DIM_];
__device__ __align__(16) __half g_q   [(size_t)BH_ * N_ * D_];       // [bh][n][d], pre-scaled*log2e
__device__ __align__(16) __half g_k   [(size_t)BH_ * N_ * D_];       // [bh][n][d]
__device__ __align__(16) __half g_v   [(size_t)BH_ * N_ * D_];       // [bh][n][d]
__device__ __align__(16) __half g_bias16[(size_t)H_ * N_ * N_];      // gathered bias * log2e, fp16
__device__ __align__(16) __half g_ao  [(size_t)ROWS_ * DIM_];        // attn out [b,n,h*D+d]

// ---------------- helpers ----------------
DEV_INLINE uint32_t smem_u32(const void* p) {
    return (uint32_t)__cvta_generic_to_shared(p);
}
DEV_INLINE void cp16(void* s, const void* g) {
    asm volatile("cp.async.cg.shared.global [%0], [%1], 16;\n"
                 :: "r"(smem_u32(s)), "l"(g));
}
DEV_INLINE void cp_commit() { asm volatile("cp.async.commit_group;\n"); }
template <int n>
DEV_INLINE void cp_wait() { asm volatile("cp.async.wait_group %0;\n" :: "n"(n)); }

DEV_INLINE uint32_t h2_as_u32(__half2 h) {
    return *reinterpret_cast<uint32_t*>(&h);
}
DEV_INLINE float ex2f(float x) {
    float y;
    asm("ex2.approx.f32 %0, %1;" : "=f"(y) : "f"(x));
    return y;
}

DEV_INLINE void ldsm_x4(uint32_t& r0, uint32_t& r1, uint32_t& r2, uint32_t& r3, uint32_t a) {
    asm volatile("ldmatrix.sync.aligned.m8n8.x4.shared.b16 {%0,%1,%2,%3}, [%4];"
                 : "=r"(r0), "=r"(r1), "=r"(r2), "=r"(r3) : "r"(a));
}
DEV_INLINE void ldsm_x4_t(uint32_t& r0, uint32_t& r1, uint32_t& r2, uint32_t& r3, uint32_t a) {
    asm volatile("ldmatrix.sync.aligned.m8n8.x4.trans.shared.b16 {%0,%1,%2,%3}, [%4];"
                 : "=r"(r0), "=r"(r1), "=r"(r2), "=r"(r3) : "r"(a));
}
DEV_INLINE void mma16816(float* c, const uint32_t* a, const uint32_t* b) {
    asm volatile(
        "mma.sync.aligned.m16n8k16.row.col.f32.f16.f16.f32 "
        "{%0,%1,%2,%3}, {%4,%5,%6,%7}, {%8,%9}, {%0,%1,%2,%3};"
        : "+f"(c[0]), "+f"(c[1]), "+f"(c[2]), "+f"(c[3])
        : "r"(a[0]), "r"(a[1]), "r"(a[2]), "r"(a[3]), "r"(b[0]), "r"(b[1]));
}

DEV_INLINE float warp_sum(float v) {
    #pragma unroll
    for (int o = 16; o; o >>= 1) v += __shfl_xor_sync(0xFFFFFFFFu, v, o);
    return v;
}
DEV_INLINE float block_sum(float v, float* sred, int tid) {
    int lane = tid & 31, w = tid >> 5;
    v = warp_sum(v);
    if (lane == 0) sred[w] = v;
    __syncthreads();
    float r = sred[0];
    #pragma unroll
    for (int i = 1; i < 8; i++) r += sred[i];
    __syncthreads();
    return r;
}

// ---------------- weight fp32 -> fp16 conversion ----------------
__global__ void cvt_kernel(const float4* __restrict__ qkv_w, const float4* __restrict__ proj_w) {
    int i = blockIdx.x * blockDim.x + threadIdx.x;
    const int n1 = DIM_ * QKV_OUT_ / 4;
    const int n2 = DIM_ * DIM_ / 4;
    if (i < n1) {
        float4 v = qkv_w[i];
        __half2* dst = (__half2*)g_wqkv;
        dst[2 * i]     = __floats2half2_rn(v.x, v.y);
        dst[2 * i + 1] = __floats2half2_rn(v.z, v.w);
    } else if (i < n1 + n2) {
        int j = i - n1;
        float4 v = proj_w[j];
        __half2* dst = (__half2*)g_wproj;
        dst[2 * j]     = __floats2half2_rn(v.x, v.y);
        dst[2 * j + 1] = __floats2half2_rn(v.z, v.w);
    }
}

// ------- gather attention bias (scaled by log2e) to fp16 [h][i][j] -------
__global__ void bias16_kernel(const float* __restrict__ att_bias,
                              const int* __restrict__ idxs, int n_off) {
    int ij = blockIdx.x * 256 + threadIdx.x;
    int h  = blockIdx.y;
    g_bias16[(size_t)h * N_ * N_ + ij] =
        __float2half(att_bias[h * n_off + idxs[ij]] * LOG2E_);
}

// ---------------- LayerNorm ----------------
__global__ void ln_kernel(const float* __restrict__ x,
                          const float* __restrict__ gamma,
                          const float* __restrict__ beta) {
    __shared__ float sred[8];
    int row = blockIdx.x;
    int tid = threadIdx.x;
    const float4* x4 = (const float4*)(x + (size_t)row * DIM_);
    float4 v0 = x4[tid];
    float4 v1 = x4[tid + 256];

    float s = v0.x + v0.y + v0.z + v0.w + v1.x + v1.y + v1.z + v1.w;
    float q = v0.x*v0.x + v0.y*v0.y + v0.z*v0.z + v0.w*v0.w
            + v1.x*v1.x + v1.y*v1.y + v1.z*v1.z + v1.w*v1.w;

    float tot_s = block_sum(s, sred, tid);
    float tot_q = block_sum(q, sred, tid);
    float mean = tot_s * (1.0f / DIM_);
    float var  = tot_q * (1.0f / DIM_) - mean * mean;
    float rstd = rsqrtf(var + LN_EPS_);

    const float4* g4 = (const float4*)gamma;
    const float4* b4 = (const float4*)beta;
    float4 ga = g4[tid], gb = g4[tid + 256];
    float4 ba = b4[tid], bb = b4[tid + 256];

    __half2* o2 = (__half2*)(g_xn + (size_t)row * DIM_);
    o2[2 * tid]       = __floats2half2_rn((v0.x - mean) * rstd * ga.x + ba.x,
                                          (v0.y - mean) * rstd * ga.y + ba.y);
    o2[2 * tid + 1]   = __floats2half2_rn((v0.z - mean) * rstd * ga.z + ba.z,
                                          (v0.w - mean) * rstd * ga.w + ba.w);
    o2[512 + 2 * tid]     = __floats2half2_rn((v1.x - mean) * rstd * gb.x + bb.x,
                                              (v1.y - mean) * rstd * gb.y + bb.y);
    o2[512 + 2 * tid + 1] = __floats2half2_rn((v1.z - mean) * rstd * gb.z + bb.z,
                                              (v1.w - mean) * rstd * gb.w + bb.w);
}

// ------- dense GEMMs (QKV / proj): 4-stage cp.async, ONE barrier/iter -------
enum { EPI_QKV = 0, EPI_PROJ = 1 };

constexpr int AS_STAGE_B = 128 * 40 * 2;   // 10240
constexpr int BS_STAGE_B = 32 * 136 * 2;   //  8704
constexpr int AS_TOT_B   = 4 * AS_STAGE_B; // 40960
constexpr int GEMM_SMEM  = AS_TOT_B + 4 * BS_STAGE_B;  // 75776

template <int EPI>
__global__ void __launch_bounds__(256, 2)
gemm_f16(const float* __restrict__ bias, float* __restrict__ outf) {
    constexpr int K   = 2048;
    constexpr int LDA = 2048;
    constexpr int LDB = (EPI == EPI_QKV) ? 6144 : 2048;
    constexpr int NT  = K / 32;   // 64 k-tiles

    extern __shared__ __align__(16) char dynsm[];

    const int bm = blockIdx.y * 128;
    const int bn = blockIdx.x * 128;

    const __half* __restrict__ A  = (EPI == EPI_QKV) ? g_xn : g_ao;
    const __half* __restrict__ Bp = (EPI == EPI_QKV) ? g_wqkv : g_wproj;

    const int tid  = threadIdx.x;
    const int lane = tid & 31;
    const int warp = tid >> 5;
    const int wm = warp & 3;
    const int wn = warp >> 2;

    float acc[2][8][4];
    #pragma unroll
    for (int i = 0; i < 2; i++)
        #pragma unroll
        for (int j = 0; j < 8; j++)
            #pragma unroll
            for (int r = 0; r < 4; r++) acc[i][j][r] = 0.0f;

    auto As = [&](int s) -> __half (*)[40] {
        return reinterpret_cast<__half(*)[40]>(dynsm + s * AS_STAGE_B);
    };
    auto Bs = [&](int s) -> __half (*)[136] {
        return reinterpret_cast<__half(*)[136]>(dynsm + AS_TOT_B + s * BS_STAGE_B);
    };

    auto load_tile = [&](int s, int k0) {
        __half (*as)[40]  = As(s);
        __half (*bs)[136] = Bs(s);
        #pragma unroll
        for (int i = 0; i < 2; i++) {
            int lin = tid + i * 256;
            int m  = lin >> 2;
            int kq = (lin & 3) << 3;
            cp16(&as[m][kq], &A[(size_t)(bm + m) * LDA + k0 + kq]);
        }
        #pragma unroll
        for (int i = 0; i < 2; i++) {
            int lin = tid + i * 256;
            int kk = lin >> 4;
            int cq = (lin & 15) << 3;
            cp16(&bs[kk][cq], &Bp[(size_t)(k0 + kk) * LDB + bn + cq]);
        }
        cp_commit();
    };

    load_tile(0, 0);
    load_tile(1, 32);
    load_tile(2, 64);

    #pragma unroll 1
    for (int t = 0; t < NT; t++) {
        if (t <= NT - 3)      cp_wait<2>();
        else if (t == NT - 2) cp_wait<1>();
        else                  cp_wait<0>();
        __syncthreads();   // single barrier per iteration

        if (t + 3 < NT) load_tile((t + 3) & 3, (t + 3) * 32);

        const int s = t & 3;
        __half (*as)[40]  = As(s);
        __half (*bs)[136] = Bs(s);
        #pragma unroll
        for (int ks = 0; ks < 2; ks++) {
            uint32_t af[2][4];
            #pragma unroll
            for (int mf = 0; mf < 2; mf++) {
                uint32_t addr = smem_u32(
                    &as[wm * 32 + mf * 16 + (lane & 15)][ks * 16 + ((lane >> 4) << 3)]);
                ldsm_x4(af[mf][0], af[mf][1], af[mf][2], af[mf][3], addr);
            }
            uint32_t bf[8][2];
            #pragma unroll
            for (int np = 0; np < 4; np++) {
                uint32_t addr = smem_u32(
                    &bs[ks * 16 + (lane & 15)][wn * 64 + np * 16 + ((lane >> 4) << 3)]);
                uint32_t r0, r1, r2, r3;
                ldsm_x4_t(r0, r1, r2, r3, addr);
                bf[np * 2][0] = r0;     bf[np * 2][1] = r1;
                bf[np * 2 + 1][0] = r2; bf[np * 2 + 1][1] = r3;
            }
            #pragma unroll
            for (int mf = 0; mf < 2; mf++)
                #pragma unroll
                for (int nf = 0; nf < 8; nf++)
                    mma16816(acc[mf][nf], af[mf], bf[nf]);
        }
    }

    // epilogue
    const int g     = lane >> 2;
    const int cpair = (lane & 3) << 1;
    #pragma unroll
    for (int mf = 0; mf < 2; mf++)
        #pragma unroll
        for (int nf = 0; nf < 8; nf++) {
            int row0 = bm + wm * 32 + mf * 16 + g;
            int col  = bn + wn * 64 + nf * 8 + cpair;
            #pragma unroll
            for (int rr = 0; rr < 2; rr++) {
                int row = row0 + rr * 8;
                float v0 = acc[mf][nf][rr * 2];
                float v1 = acc[mf][nf][rr * 2 + 1];
                if constexpr (EPI == EPI_QKV) {
                    v0 += bias[col];
                    v1 += bias[col + 1];
                    int tsel = col >> 11;
                    int r = col & 2047;
                    int h = r >> 7, d = r & 127;
                    int b = row >> 10, n = row & 1023;
                    int bhi = (b << 4) + h;
                    size_t off = ((size_t)bhi * N_ + n) * D_ + d;
                    if (tsel == 0) {
                        *(__half2*)&g_q[off] = __floats2half2_rn(v0 * QSC_, v1 * QSC_);
                    } else if (tsel == 1) {
                        *(__half2*)&g_k[off] = __floats2half2_rn(v0, v1);
                    } else {
                        *(__half2*)&g_v[off] = __floats2half2_rn(v0, v1);
                    }
                } else {
                    float2 o;
                    o.x = v0 + bias[col];
                    o.y = v1 + bias[col + 1];
                    *(float2*)&outf[(size_t)row * DIM_ + col] = o;
                }
            }
        }
}

// ---------------- fused flash attention (R9 form, log2-domain softmax) ----------------
constexpr int FL_STRIDE = 136;
constexpr int FL_TILE   = 128 * FL_STRIDE;
constexpr int FL_STAGE  = 3 * FL_TILE;               // K + V + bias
constexpr int FL_SMEM_BYTES = 2 * FL_STAGE * 2;      // 208896

__global__ void __launch_bounds__(256, 1)
flash_kernel() {
    extern __shared__ char g_smem[];
    __half* sm = (__half*)g_smem;

    const int tid  = threadIdx.x;
    const int lane = tid & 31;
    const int w    = tid >> 5;
    const int qt   = blockIdx.x;
    const int bh   = blockIdx.y;
    const int h    = bh & 15;
    const int b    = bh >> 4;

    const __half* __restrict__ Qp = g_q + ((size_t)bh * N_ + qt * 128) * D_;
    const __half* __restrict__ Kp = g_k + (size_t)bh * N_ * D_;
    const __half* __restrict__ Vp = g_v + (size_t)bh * N_ * D_;
    const __half* __restrict__ Bb = g_bias16 + (size_t)h * N_ * N_ + (size_t)(qt * 128) * N_;

    // ---- stage Q through smem, extract register fragments ----
    {
        __half* sQ = sm;
        #pragma unroll
        for (int i = 0; i < 8; i++) {
            int chunk = tid + i * 256;
            int r  = chunk >> 4;
            int c8 = (chunk & 15) << 3;
            *(float4*)&sQ[r * FL_STRIDE + c8] = *(const float4*)&Qp[r * D_ + c8];
        }
    }
    __syncthreads();
    uint32_t aq[8][4];
    #pragma unroll
    for (int kc = 0; kc < 8; kc++) {
        uint32_t addr = smem_u32(
            &sm[(w * 16 + (lane & 15)) * FL_STRIDE + kc * 16 + ((lane >> 4) << 3)]);
        ldsm_x4(aq[kc][0], aq[kc][1], aq[kc][2], aq[kc][3], addr);
    }
    __syncthreads();

    auto load_kv = [&](int s, int jt) {
        __half* sK = sm + s * FL_STAGE;
        __half* sV = sK + FL_TILE;
        __half* sB = sV + FL_TILE;
        #pragma unroll
        for (int i = 0; i < 8; i++) {
            int chunk = tid + i * 256;
            int r  = chunk >> 4;
            int c8 = (chunk & 15) << 3;
            cp16(&sK[r * FL_STRIDE + c8], &Kp[(size_t)(jt * 128 + r) * D_ + c8]);
        }
        #pragma unroll
        for (int i = 0; i < 8; i++) {
            int chunk = tid + i * 256;
            int r  = chunk >> 4;
            int c8 = (chunk & 15) << 3;
            cp16(&sV[r * FL_STRIDE + c8], &Vp[(size_t)(jt * 128 + r) * D_ + c8]);
        }
        #pragma unroll
        for (int i = 0; i < 8; i++) {
            int chunk = tid + i * 256;
            int r  = chunk >> 4;
            int c8 = (chunk & 15) << 3;
            cp16(&sB[r * FL_STRIDE + c8], &Bb[(size_t)r * N_ + jt * 128 + c8]);
        }
        cp_commit();
    };

    float acc_o[16][4];
    #pragma unroll
    for (int i = 0; i < 16; i++)
        #pragma unroll
        for (int r = 0; r < 4; r++) acc_o[i][r] = 0.0f;
    float m0 = -1e30f, m1 = -1e30f, l0 = 0.0f, l1 = 0.0f;

    const int g = lane >> 2;

    load_kv(0, 0);

    #pragma unroll 1
    for (int jt = 0; jt < 8; jt++) {
        if (jt + 1 < 8) { load_kv((jt + 1) & 1, jt + 1); cp_wait<1>(); }
        else            { cp_wait<0>(); }
        __syncthreads();

        const __half* sK = sm + (jt & 1) * FL_STAGE;
        const __half* sV = sK + FL_TILE;
        const __half* sB = sV + FL_TILE;

        // ---- S = Q K^T (16 x 128 per warp), logits already in log2 domain ----
        float accs[16][4];
        #pragma unroll
        for (int i = 0; i < 16; i++)
            #pragma unroll
            for (int r = 0; r < 4; r++) accs[i][r] = 0.0f;

        #pragma unroll
        for (int kc = 0; kc < 8; kc++) {
            #pragma unroll
            for (int nf2 = 0; nf2 < 8; nf2++) {
                uint32_t r0, r1, r2, r3;
                uint32_t addr = smem_u32(
                    &sK[(nf2 * 16 + (lane & 15)) * FL_STRIDE + kc * 16 + ((lane >> 4) << 3)]);
                ldsm_x4(r0, r1, r2, r3, addr);
                uint32_t bA[2] = {r0, r2}, bB[2] = {r1, r3};
                mma16816(accs[nf2 * 2],     aq[kc], bA);
                mma16816(accs[nf2 * 2 + 1], aq[kc], bB);
            }
        }

        // ---- bias add (from smem) + online softmax (base-2) ----
        const int cpair = (lane & 3) << 1;
        const __half* srow0 = sB + (size_t)(w * 16 + g) * FL_STRIDE;
        const __half* srow1 = srow0 + 8 * FL_STRIDE;
        float mx0 = -1e30f, mx1 = -1e30f;
        #pragma unroll
        for (int nf = 0; nf < 16; nf++) {
            int col = nf * 8 + cpair;
            __half2 b0 = *(const __half2*)&srow0[col];
            __half2 b1 = *(const __half2*)&srow1[col];
            accs[nf][0] += __low2float(b0);
            accs[nf][1] += __high2float(b0);
            accs[nf][2] += __low2float(b1);
            accs[nf][3] += __high2float(b1);
            mx0 = fmaxf(mx0, fmaxf(accs[nf][0], accs[nf][1]));
            mx1 = fmaxf(mx1, fmaxf(accs[nf][2], accs[nf][3]));
        }
        mx0 = fmaxf(mx0, __shfl_xor_sync(0xFFFFFFFFu, mx0, 1));
        mx0 = fmaxf(mx0, __shfl_xor_sync(0xFFFFFFFFu, mx0, 2));
        mx1 = fmaxf(mx1, __shfl_xor_sync(0xFFFFFFFFu, mx1, 1));
        mx1 = fmaxf(mx1, __shfl_xor_sync(0xFFFFFFFFu, mx1, 2));

        float mn0 = fmaxf(m0, mx0), mn1 = fmaxf(m1, mx1);
        float sc0 = ex2f(m0 - mn0), sc1 = ex2f(m1 - mn1);
        m0 = mn0; m1 = mn1;

        float sum0 = 0.0f, sum1 = 0.0f;
        uint32_t ph[8][4];
        #pragma unroll
        for (int nf = 0; nf < 16; nf++) {
            float p0 = ex2f(accs[nf][0] - m0);
            float p1 = ex2f(accs[nf][1] - m0);
            float p2 = ex2f(accs[nf][2] - m1);
            float p3 = ex2f(accs[nf][3] - m1);
            sum0 += p0 + p1;
            sum1 += p2 + p3;
            uint32_t lo = h2_as_u32(__floats2half2_rn(p0, p1));
            uint32_t hi = h2_as_u32(__floats2half2_rn(p2, p3));
            int kc = nf >> 1;
            if ((nf & 1) == 0) { ph[kc][0] = lo; ph[kc][1] = hi; }
            else               { ph[kc][2] = lo; ph[kc][3] = hi; }
        }
        sum0 += __shfl_xor_sync(0xFFFFFFFFu, sum0, 1);
        sum0 += __shfl_xor_sync(0xFFFFFFFFu, sum0, 2);
        sum1 += __shfl_xor_sync(0xFFFFFFFFu, sum1, 1);
        sum1 += __shfl_xor_sync(0xFFFFFFFFu, sum1, 2);
        l0 = l0 * sc0 + sum0;
        l1 = l1 * sc1 + sum1;

        #pragma unroll
        for (int nf = 0; nf < 16; nf++) {
            acc_o[nf][0] *= sc0; acc_o[nf][1] *= sc0;
            acc_o[nf][2] *= sc1; acc_o[nf][3] *= sc1;
        }

        // ---- O += P V ----
        #pragma unroll
        for (int kc = 0; kc < 8; kc++) {
            #pragma unroll
            for (int nf2 = 0; nf2 < 8; nf2++) {
                uint32_t r0, r1, r2, r3;
                uint32_t addr = smem_u32(
                    &sV[(kc * 16 + (lane & 15)) * FL_STRIDE + nf2 * 16 + ((lane >> 4) << 3)]);
                ldsm_x4_t(r0, r1, r2, r3, addr);
                uint32_t bA[2] = {r0, r1}, bB[2] = {r2, r3};
                mma16816(acc_o[nf2 * 2],     ph[kc], bA);
                mma16816(acc_o[nf2 * 2 + 1], ph[kc], bB);
            }
        }
        __syncthreads();
    }

    // ---- normalize + write [b, n, h*128+d] ----
    float inv0 = __frcp_rn(l0), inv1 = __frcp_rn(l1);
    const int cpair = (lane & 3) << 1;
    int n0 = qt * 128 + w * 16 + g;
    __half* dst0 = g_ao + ((size_t)(b * N_ + n0)) * DIM_ + h * D_;
    __half* dst1 = dst0 + (size_t)8 * DIM_;
    #pragma unroll
    for (int nf = 0; nf < 16; nf++) {
        int col = nf * 8 + cpair;
        *(__half2*)&dst0[col] = __floats2half2_rn(acc_o[nf][0] * inv0, acc_o[nf][1] * inv0);
        *(__half2*)&dst1[col] = __floats2half2_rn(acc_o[nf][2] * inv1, acc_o[nf][3] * inv1);
    }
}

// ---------------- launch ----------------
extern "C" void kernel_launch(void* const* d_in, const int* in_sizes, int n_in,
                              void* d_out, int out_size) {
    const float* x        = (const float*)d_in[0];
    const float* ln_g     = (const float*)d_in[1];
    const float* ln_b     = (const float*)d_in[2];
    const float* qkv_w    = (const float*)d_in[3];
    const float* qkv_b    = (const float*)d_in[4];
    const float* proj_w   = (const float*)d_in[5];
    const float* proj_b   = (const float*)d_in[6];
    const float* att_bias = (const float*)d_in[7];
    const int*   bias_idx = (const int*)d_in[8];
    float* out = (float*)d_out;

    int n_off = in_sizes[7] / H_;   // 1024

    cudaFuncSetAttribute(flash_kernel,
                         cudaFuncAttributeMaxDynamicSharedMemorySize, FL_SMEM_BYTES);
    cudaFuncSetAttribute(gemm_f16<EPI_QKV>,
                         cudaFuncAttributeMaxDynamicSharedMemorySize, GEMM_SMEM);
    cudaFuncSetAttribute(gemm_f16<EPI_PROJ>,
                         cudaFuncAttributeMaxDynamicSharedMemorySize, GEMM_SMEM);

    // 1. weights -> fp16
    cvt_kernel<<<16384, 256>>>((const float4*)qkv_w, (const float4*)proj_w);
    // 2. LayerNorm -> fp16
    ln_kernel<<<ROWS_, 256>>>(x, ln_g, ln_b);
    // 3. gather bias (log2-scaled) -> fp16 [h][i][j]
    bias16_kernel<<<dim3(N_ * N_ / 256, H_), 256>>>(att_bias, bias_idx, n_off);
    // 4. QKV GEMM -> q(scaled*log2e)/k/v [bh][n][d]
    gemm_f16<EPI_QKV><<<dim3(QKV_OUT_ / 128, ROWS_ / 128), 256, GEMM_SMEM>>>(
        qkv_b, nullptr);
    // 5. fused attention (base-2 softmax)
    flash_kernel<<<dim3(N_ / 128, BH_), 256, FL_SMEM_BYTES>>>();
    // 6. out = AO @ proj_w + proj_b
    gemm_f16<EPI_PROJ><<<dim3(DIM_ / 128, ROWS_ / 128), 256, GEMM_SMEM>>>(
        proj_b, out);
}

// round 13
// speedup vs baseline: 1.0429x; 1.0006x over previous
#include <cuda_runtime.h>
#include <cuda_fp16.h>
#include <cstdint>

#define DEV_INLINE __device__ __forceinline__

// Problem constants
constexpr int B_    = 16;
constexpr int N_    = 1024;
constexpr int H_    = 16;
constexpr int D_    = 128;
constexpr int DIM_  = 2048;
constexpr int QKV_OUT_ = 6144;
constexpr int ROWS_ = B_ * N_;     // 16384
constexpr int BH_   = B_ * H_;     // 256
constexpr float LOG2E_ = 1.4426950408889634f;
constexpr float SCALE_ = 0.08838834764831845f;          // 128^-0.5
constexpr float QSC_   = SCALE_ * LOG2E_;               // q pre-scale, log2 domain
constexpr float LN_EPS_ = 1e-5f;

// ---------------- device scratch (static, no allocs) ----------------
__device__ __align__(16) __half g_xn  [(size_t)ROWS_ * DIM_];
__device__ __align__(16) __half g_wqkv[(size_t)DIM_ * QKV_OUT_];
__device__ __align__(16) __half g_wproj[(size_t)DIM_ * DIM_];
__device__ __align__(16) __half g_q   [(size_t)BH_ * N_ * D_];       // [bh][n][d], pre-scaled*log2e
__device__ __align__(16) __half g_k   [(size_t)BH_ * N_ * D_];       // [bh][n][d]
__device__ __align__(16) __half g_v   [(size_t)BH_ * N_ * D_];       // [bh][n][d]
__device__ __align__(16) __half g_bias16[(size_t)H_ * N_ * N_];      // gathered bias * log2e, fp16
__device__ __align__(16) __half g_ao  [(size_t)ROWS_ * DIM_];        // attn out [b,n,h*D+d]

// ---------------- helpers ----------------
DEV_INLINE uint32_t smem_u32(const void* p) {
    return (uint32_t)__cvta_generic_to_shared(p);
}
DEV_INLINE void cp16(void* s, const void* g) {
    asm volatile("cp.async.cg.shared.global [%0], [%1], 16;\n"
                 :: "r"(smem_u32(s)), "l"(g));
}
DEV_INLINE void cp_commit() { asm volatile("cp.async.commit_group;\n"); }
template <int n>
DEV_INLINE void cp_wait() { asm volatile("cp.async.wait_group %0;\n" :: "n"(n)); }

DEV_INLINE uint32_t h2_as_u32(__half2 h) {
    return *reinterpret_cast<uint32_t*>(&h);
}
DEV_INLINE float ex2f(float x) {
    float y;
    asm("ex2.approx.f32 %0, %1;" : "=f"(y) : "f"(x));
    return y;
}

DEV_INLINE void ldsm_x4(uint32_t& r0, uint32_t& r1, uint32_t& r2, uint32_t& r3, uint32_t a) {
    asm volatile("ldmatrix.sync.aligned.m8n8.x4.shared.b16 {%0,%1,%2,%3}, [%4];"
                 : "=r"(r0), "=r"(r1), "=r"(r2), "=r"(r3) : "r"(a));
}
DEV_INLINE void ldsm_x4_t(uint32_t& r0, uint32_t& r1, uint32_t& r2, uint32_t& r3, uint32_t a) {
    asm volatile("ldmatrix.sync.aligned.m8n8.x4.trans.shared.b16 {%0,%1,%2,%3}, [%4];"
                 : "=r"(r0), "=r"(r1), "=r"(r2), "=r"(r3) : "r"(a));
}
DEV_INLINE void mma16816(float* c, const uint32_t* a, const uint32_t* b) {
    asm volatile(
        "mma.sync.aligned.m16n8k16.row.col.f32.f16.f16.f32 "
        "{%0,%1,%2,%3}, {%4,%5,%6,%7}, {%8,%9}, {%0,%1,%2,%3};"
        : "+f"(c[0]), "+f"(c[1]), "+f"(c[2]), "+f"(c[3])
        : "r"(a[0]), "r"(a[1]), "r"(a[2]), "r"(a[3]), "r"(b[0]), "r"(b[1]));
}

DEV_INLINE float warp_sum(float v) {
    #pragma unroll
    for (int o = 16; o; o >>= 1) v += __shfl_xor_sync(0xFFFFFFFFu, v, o);
    return v;
}
DEV_INLINE float block_sum(float v, float* sred, int tid) {
    int lane = tid & 31, w = tid >> 5;
    v = warp_sum(v);
    if (lane == 0) sred[w] = v;
    __syncthreads();
    float r = sred[0];
    #pragma unroll
    for (int i = 1; i < 8; i++) r += sred[i];
    __syncthreads();
    return r;
}

// ---------------- weight fp32 -> fp16 conversion ----------------
__global__ void cvt_kernel(const float4* __restrict__ qkv_w, const float4* __restrict__ proj_w) {
    int i = blockIdx.x * blockDim.x + threadIdx.x;
    const int n1 = DIM_ * QKV_OUT_ / 4;
    const int n2 = DIM_ * DIM_ / 4;
    if (i < n1) {
        float4 v = qkv_w[i];
        __half2* dst = (__half2*)g_wqkv;
        dst[2 * i]     = __floats2half2_rn(v.x, v.y);
        dst[2 * i + 1] = __floats2half2_rn(v.z, v.w);
    } else if (i < n1 + n2) {
        int j = i - n1;
        float4 v = proj_w[j];
        __half2* dst = (__half2*)g_wproj;
        dst[2 * j]     = __floats2half2_rn(v.x, v.y);
        dst[2 * j + 1] = __floats2half2_rn(v.z, v.w);
    }
}

// ------- gather attention bias (scaled by log2e) to fp16 [h][i][j] -------
__global__ void bias16_kernel(const float* __restrict__ att_bias,
                              const int* __restrict__ idxs, int n_off) {
    int ij = blockIdx.x * 256 + threadIdx.x;
    int h  = blockIdx.y;
    g_bias16[(size_t)h * N_ * N_ + ij] =
        __float2half(att_bias[h * n_off + idxs[ij]] * LOG2E_);
}

// ---------------- LayerNorm ----------------
__global__ void ln_kernel(const float* __restrict__ x,
                          const float* __restrict__ gamma,
                          const float* __restrict__ beta) {
    __shared__ float sred[8];
    int row = blockIdx.x;
    int tid = threadIdx.x;
    const float4* x4 = (const float4*)(x + (size_t)row * DIM_);
    float4 v0 = x4[tid];
    float4 v1 = x4[tid + 256];

    float s = v0.x + v0.y + v0.z + v0.w + v1.x + v1.y + v1.z + v1.w;
    float q = v0.x*v0.x + v0.y*v0.y + v0.z*v0.z + v0.w*v0.w
            + v1.x*v1.x + v1.y*v1.y + v1.z*v1.z + v1.w*v1.w;

    float tot_s = block_sum(s, sred, tid);
    float tot_q = block_sum(q, sred, tid);
    float mean = tot_s * (1.0f / DIM_);
    float var  = tot_q * (1.0f / DIM_) - mean * mean;
    float rstd = rsqrtf(var + LN_EPS_);

    const float4* g4 = (const float4*)gamma;
    const float4* b4 = (const float4*)beta;
    float4 ga = g4[tid], gb = g4[tid + 256];
    float4 ba = b4[tid], bb = b4[tid + 256];

    __half2* o2 = (__half2*)(g_xn + (size_t)row * DIM_);
    o2[2 * tid]       = __floats2half2_rn((v0.x - mean) * rstd * ga.x + ba.x,
                                          (v0.y - mean) * rstd * ga.y + ba.y);
    o2[2 * tid + 1]   = __floats2half2_rn((v0.z - mean) * rstd * ga.z + ba.z,
                                          (v0.w - mean) * rstd * ga.w + ba.w);
    o2[512 + 2 * tid]     = __floats2half2_rn((v1.x - mean) * rstd * gb.x + bb.x,
                                              (v1.y - mean) * rstd * gb.y + bb.y);
    o2[512 + 2 * tid + 1] = __floats2half2_rn((v1.z - mean) * rstd * gb.z + bb.z,
                                              (v1.w - mean) * rstd * gb.w + bb.w);
}

// ------- dense GEMMs (QKV / proj): 4-stage cp.async, ONE barrier/iter -------
enum { EPI_QKV = 0, EPI_PROJ = 1 };

constexpr int AS_STAGE_B = 128 * 40 * 2;   // 10240
constexpr int BS_STAGE_B = 32 * 136 * 2;   //  8704
constexpr int AS_TOT_B   = 4 * AS_STAGE_B; // 40960
constexpr int GEMM_SMEM  = AS_TOT_B + 4 * BS_STAGE_B;  // 75776

template <int EPI>
__global__ void __launch_bounds__(256, 2)
gemm_f16(const float* __restrict__ bias, float* __restrict__ outf) {
    constexpr int K   = 2048;
    constexpr int LDA = 2048;
    constexpr int LDB = (EPI == EPI_QKV) ? 6144 : 2048;
    constexpr int NT  = K / 32;   // 64 k-tiles

    extern __shared__ __align__(16) char dynsm[];

    const int bm = blockIdx.y * 128;
    const int bn = blockIdx.x * 128;

    const __half* __restrict__ A  = (EPI == EPI_QKV) ? g_xn : g_ao;
    const __half* __restrict__ Bp = (EPI == EPI_QKV) ? g_wqkv : g_wproj;

    const int tid  = threadIdx.x;
    const int lane = tid & 31;
    const int warp = tid >> 5;
    const int wm = warp & 3;
    const int wn = warp >> 2;

    float acc[2][8][4];
    #pragma unroll
    for (int i = 0; i < 2; i++)
        #pragma unroll
        for (int j = 0; j < 8; j++)
            #pragma unroll
            for (int r = 0; r < 4; r++) acc[i][j][r] = 0.0f;

    auto As = [&](int s) -> __half (*)[40] {
        return reinterpret_cast<__half(*)[40]>(dynsm + s * AS_STAGE_B);
    };
    auto Bs = [&](int s) -> __half (*)[136] {
        return reinterpret_cast<__half(*)[136]>(dynsm + AS_TOT_B + s * BS_STAGE_B);
    };

    auto load_tile = [&](int s, int k0) {
        __half (*as)[40]  = As(s);
        __half (*bs)[136] = Bs(s);
        #pragma unroll
        for (int i = 0; i < 2; i++) {
            int lin = tid + i * 256;
            int m  = lin >> 2;
            int kq = (lin & 3) << 3;
            cp16(&as[m][kq], &A[(size_t)(bm + m) * LDA + k0 + kq]);
        }
        #pragma unroll
        for (int i = 0; i < 2; i++) {
            int lin = tid + i * 256;
            int kk = lin >> 4;
            int cq = (lin & 15) << 3;
            cp16(&bs[kk][cq], &Bp[(size_t)(k0 + kk) * LDB + bn + cq]);
        }
        cp_commit();
    };

    load_tile(0, 0);
    load_tile(1, 32);
    load_tile(2, 64);

    #pragma unroll 1
    for (int t = 0; t < NT; t++) {
        if (t <= NT - 3)      cp_wait<2>();
        else if (t == NT - 2) cp_wait<1>();
        else                  cp_wait<0>();
        __syncthreads();   // single barrier per iteration

        if (t + 3 < NT) load_tile((t + 3) & 3, (t + 3) * 32);

        const int s = t & 3;
        __half (*as)[40]  = As(s);
        __half (*bs)[136] = Bs(s);
        #pragma unroll
        for (int ks = 0; ks < 2; ks++) {
            uint32_t af[2][4];
            #pragma unroll
            for (int mf = 0; mf < 2; mf++) {
                uint32_t addr = smem_u32(
                    &as[wm * 32 + mf * 16 + (lane & 15)][ks * 16 + ((lane >> 4) << 3)]);
                ldsm_x4(af[mf][0], af[mf][1], af[mf][2], af[mf][3], addr);
            }
            uint32_t bf[8][2];
            #pragma unroll
            for (int np = 0; np < 4; np++) {
                uint32_t addr = smem_u32(
                    &bs[ks * 16 + (lane & 15)][wn * 64 + np * 16 + ((lane >> 4) << 3)]);
                uint32_t r0, r1, r2, r3;
                ldsm_x4_t(r0, r1, r2, r3, addr);
                bf[np * 2][0] = r0;     bf[np * 2][1] = r1;
                bf[np * 2 + 1][0] = r2; bf[np * 2 + 1][1] = r3;
            }
            #pragma unroll
            for (int mf = 0; mf < 2; mf++)
                #pragma unroll
                for (int nf = 0; nf < 8; nf++)
                    mma16816(acc[mf][nf], af[mf], bf[nf]);
        }
    }

    // epilogue
    const int g     = lane >> 2;
    const int cpair = (lane & 3) << 1;
    #pragma unroll
    for (int mf = 0; mf < 2; mf++)
        #pragma unroll
        for (int nf = 0; nf < 8; nf++) {
            int row0 = bm + wm * 32 + mf * 16 + g;
            int col  = bn + wn * 64 + nf * 8 + cpair;
            #pragma unroll
            for (int rr = 0; rr < 2; rr++) {
                int row = row0 + rr * 8;
                float v0 = acc[mf][nf][rr * 2];
                float v1 = acc[mf][nf][rr * 2 + 1];
                if constexpr (EPI == EPI_QKV) {
                    v0 += bias[col];
                    v1 += bias[col + 1];
                    int tsel = col >> 11;
                    int r = col & 2047;
                    int h = r >> 7, d = r & 127;
                    int b = row >> 10, n = row & 1023;
                    int bhi = (b << 4) + h;
                    size_t off = ((size_t)bhi * N_ + n) * D_ + d;
                    if (tsel == 0) {
                        *(__half2*)&g_q[off] = __floats2half2_rn(v0 * QSC_, v1 * QSC_);
                    } else if (tsel == 1) {
                        *(__half2*)&g_k[off] = __floats2half2_rn(v0, v1);
                    } else {
                        *(__half2*)&g_v[off] = __floats2half2_rn(v0, v1);
                    }
                } else {
                    float2 o;
                    o.x = v0 + bias[col];
                    o.y = v1 + bias[col + 1];
                    *(float2*)&outf[(size_t)row * DIM_ + col] = o;
                }
            }
        }
}

// ---------------- fused flash attention (log2-domain softmax) ----------------
constexpr int FL_STRIDE = 136;
constexpr int FL_TILE   = 128 * FL_STRIDE;
constexpr int FL_STAGE  = 3 * FL_TILE;               // K + V + bias
constexpr int FL_SMEM_BYTES = 2 * FL_STAGE * 2;      // 208896

__global__ void __launch_bounds__(256, 1)
flash_kernel() {
    extern __shared__ char g_smem[];
    __half* sm = (__half*)g_smem;

    const int tid  = threadIdx.x;
    const int lane = tid & 31;
    const int w    = tid >> 5;
    const int qt   = blockIdx.x;
    const int bh   = blockIdx.y;
    const int h    = bh & 15;
    const int b    = bh >> 4;

    const __half* __restrict__ Qp = g_q + ((size_t)bh * N_ + qt * 128) * D_;
    const __half* __restrict__ Kp = g_k + (size_t)bh * N_ * D_;
    const __half* __restrict__ Vp = g_v + (size_t)bh * N_ * D_;
    const __half* __restrict__ Bb = g_bias16 + (size_t)h * N_ * N_ + (size_t)(qt * 128) * N_;

    // ---- stage Q through smem, extract register fragments ----
    {
        __half* sQ = sm;
        #pragma unroll
        for (int i = 0; i < 8; i++) {
            int chunk = tid + i * 256;
            int r  = chunk >> 4;
            int c8 = (chunk & 15) << 3;
            *(float4*)&sQ[r * FL_STRIDE + c8] = *(const float4*)&Qp[r * D_ + c8];
        }
    }
    __syncthreads();
    uint32_t aq[8][4];
    #pragma unroll
    for (int kc = 0; kc < 8; kc++) {
        uint32_t addr = smem_u32(
            &sm[(w * 16 + (lane & 15)) * FL_STRIDE + kc * 16 + ((lane >> 4) << 3)]);
        ldsm_x4(aq[kc][0], aq[kc][1], aq[kc][2], aq[kc][3], addr);
    }
    __syncthreads();

    auto load_kv = [&](int s, int jt) {
        __half* sK = sm + s * FL_STAGE;
        __half* sV = sK + FL_TILE;
        __half* sB = sV + FL_TILE;
        #pragma unroll
        for (int i = 0; i < 8; i++) {
            int chunk = tid + i * 256;
            int r  = chunk >> 4;
            int c8 = (chunk & 15) << 3;
            cp16(&sK[r * FL_STRIDE + c8], &Kp[(size_t)(jt * 128 + r) * D_ + c8]);
        }
        #pragma unroll
        for (int i = 0; i < 8; i++) {
            int chunk = tid + i * 256;
            int r  = chunk >> 4;
            int c8 = (chunk & 15) << 3;
            cp16(&sV[r * FL_STRIDE + c8], &Vp[(size_t)(jt * 128 + r) * D_ + c8]);
        }
        #pragma unroll
        for (int i = 0; i < 8; i++) {
            int chunk = tid + i * 256;
            int r  = chunk >> 4;
            int c8 = (chunk & 15) << 3;
            cp16(&sB[r * FL_STRIDE + c8], &Bb[(size_t)r * N_ + jt * 128 + c8]);
        }
        cp_commit();
    };

    float acc_o[16][4];
    #pragma unroll
    for (int i = 0; i < 16; i++)
        #pragma unroll
        for (int r = 0; r < 4; r++) acc_o[i][r] = 0.0f;
    float m0 = -1e30f, m1 = -1e30f, l0 = 0.0f, l1 = 0.0f;

    const int g = lane >> 2;

    load_kv(0, 0);

    #pragma unroll 1
    for (int jt = 0; jt < 8; jt++) {
        if (jt + 1 < 8) { load_kv((jt + 1) & 1, jt + 1); cp_wait<1>(); }
        else            { cp_wait<0>(); }
        __syncthreads();

        const __half* sK = sm + (jt & 1) * FL_STAGE;
        const __half* sV = sK + FL_TILE;
        const __half* sB = sV + FL_TILE;

        // ---- S = Q K^T (16 x 128 per warp), logits already in log2 domain ----
        float accs[16][4];
        #pragma unroll
        for (int i = 0; i < 16; i++)
            #pragma unroll
            for (int r = 0; r < 4; r++) accs[i][r] = 0.0f;

        #pragma unroll
        for (int kc = 0; kc < 8; kc++) {
            #pragma unroll
            for (int nf2 = 0; nf2 < 8; nf2++) {
                uint32_t r0, r1, r2, r3;
                uint32_t addr = smem_u32(
                    &sK[(nf2 * 16 + (lane & 15)) * FL_STRIDE + kc * 16 + ((lane >> 4) << 3)]);
                ldsm_x4(r0, r1, r2, r3, addr);
                uint32_t bA[2] = {r0, r2}, bB[2] = {r1, r3};
                mma16816(accs[nf2 * 2],     aq[kc], bA);
                mma16816(accs[nf2 * 2 + 1], aq[kc], bB);
            }
        }

        // ---- bias add (from smem) + online softmax (base-2) ----
        const int cpair = (lane & 3) << 1;
        const __half* srow0 = sB + (size_t)(w * 16 + g) * FL_STRIDE;
        const __half* srow1 = srow0 + 8 * FL_STRIDE;
        float mx0 = -1e30f, mx1 = -1e30f;
        #pragma unroll
        for (int nf = 0; nf < 16; nf++) {
            int col = nf * 8 + cpair;
            __half2 b0 = *(const __half2*)&srow0[col];
            __half2 b1 = *(const __half2*)&srow1[col];
            accs[nf][0] += __low2float(b0);
            accs[nf][1] += __high2float(b0);
            accs[nf][2] += __low2float(b1);
            accs[nf][3] += __high2float(b1);
            mx0 = fmaxf(mx0, fmaxf(accs[nf][0], accs[nf][1]));
            mx1 = fmaxf(mx1, fmaxf(accs[nf][2], accs[nf][3]));
        }
        mx0 = fmaxf(mx0, __shfl_xor_sync(0xFFFFFFFFu, mx0, 1));
        mx0 = fmaxf(mx0, __shfl_xor_sync(0xFFFFFFFFu, mx0, 2));
        mx1 = fmaxf(mx1, __shfl_xor_sync(0xFFFFFFFFu, mx1, 1));
        mx1 = fmaxf(mx1, __shfl_xor_sync(0xFFFFFFFFu, mx1, 2));

        float mn0 = fmaxf(m0, mx0), mn1 = fmaxf(m1, mx1);
        float sc0 = ex2f(m0 - mn0), sc1 = ex2f(m1 - mn1);
        m0 = mn0; m1 = mn1;

        float sum0 = 0.0f, sum1 = 0.0f;
        uint32_t ph[8][4];
        #pragma unroll
        for (int nf = 0; nf < 16; nf++) {
            float p0 = ex2f(accs[nf][0] - m0);
            float p1 = ex2f(accs[nf][1] - m0);
            float p2 = ex2f(accs[nf][2] - m1);
            float p3 = ex2f(accs[nf][3] - m1);
            sum0 += p0 + p1;
            sum1 += p2 + p3;
            uint32_t lo = h2_as_u32(__floats2half2_rn(p0, p1));
            uint32_t hi = h2_as_u32(__floats2half2_rn(p2, p3));
            int kc = nf >> 1;
            if ((nf & 1) == 0) { ph[kc][0] = lo; ph[kc][1] = hi; }
            else               { ph[kc][2] = lo; ph[kc][3] = hi; }
        }
        sum0 += __shfl_xor_sync(0xFFFFFFFFu, sum0, 1);
        sum0 += __shfl_xor_sync(0xFFFFFFFFu, sum0, 2);
        sum1 += __shfl_xor_sync(0xFFFFFFFFu, sum1, 1);
        sum1 += __shfl_xor_sync(0xFFFFFFFFu, sum1, 2);
        l0 = l0 * sc0 + sum0;
        l1 = l1 * sc1 + sum1;

        #pragma unroll
        for (int nf = 0; nf < 16; nf++) {
            acc_o[nf][0] *= sc0; acc_o[nf][1] *= sc0;
            acc_o[nf][2] *= sc1; acc_o[nf][3] *= sc1;
        }

        // ---- O += P V ----
        #pragma unroll
        for (int kc = 0; kc < 8; kc++) {
            #pragma unroll
            for (int nf2 = 0; nf2 < 8; nf2++) {
                uint32_t r0, r1, r2, r3;
                uint32_t addr = smem_u32(
                    &sV[(kc * 16 + (lane & 15)) * FL_STRIDE + nf2 * 16 + ((lane >> 4) << 3)]);
                ldsm_x4_t(r0, r1, r2, r3, addr);
                uint32_t bA[2] = {r0, r1}, bB[2] = {r2, r3};
                mma16816(acc_o[nf2 * 2],     ph[kc], bA);
                mma16816(acc_o[nf2 * 2 + 1], ph[kc], bB);
            }
        }
        __syncthreads();
    }

    // ---- normalize + write [b, n, h*128+d] ----
    float inv0 = __frcp_rn(l0), inv1 = __frcp_rn(l1);
    const int cpair = (lane & 3) << 1;
    int n0 = qt * 128 + w * 16 + g;
    __half* dst0 = g_ao + ((size_t)(b * N_ + n0)) * DIM_ + h * D_;
    __half* dst1 = dst0 + (size_t)8 * DIM_;
    #pragma unroll
    for (int nf = 0; nf < 16; nf++) {
        int col = nf * 8 + cpair;
        *(__half2*)&dst0[col] = __floats2half2_rn(acc_o[nf][0] * inv0, acc_o[nf][1] * inv0);
        *(__half2*)&dst1[col] = __floats2half2_rn(acc_o[nf][2] * inv1, acc_o[nf][3] * inv1);
    }
}

// ---------------- launch (stream fork/join for independent prologue) ----------------
extern "C" void kernel_launch(void* const* d_in, const int* in_sizes, int n_in,
                              void* d_out, int out_size) {
    const float* x        = (const float*)d_in[0];
    const float* ln_g     = (const float*)d_in[1];
    const float* ln_b     = (const float*)d_in[2];
    const float* qkv_w    = (const float*)d_in[3];
    const float* qkv_b    = (const float*)d_in[4];
    const float* proj_w   = (const float*)d_in[5];
    const float* proj_b   = (const float*)d_in[6];
    const float* att_bias = (const float*)d_in[7];
    const int*   bias_idx = (const int*)d_in[8];
    float* out = (float*)d_out;

    int n_off = in_sizes[7] / H_;   // 1024

    static bool inited = false;
    static cudaStream_t s_bias, s_cvt;
    static cudaEvent_t e_fork, e_bias, e_cvt;
    if (!inited) {
        inited = true;
        cudaStreamCreateWithFlags(&s_bias, cudaStreamNonBlocking);
        cudaStreamCreateWithFlags(&s_cvt,  cudaStreamNonBlocking);
        cudaEventCreateWithFlags(&e_fork, cudaEventDisableTiming);
        cudaEventCreateWithFlags(&e_bias, cudaEventDisableTiming);
        cudaEventCreateWithFlags(&e_cvt,  cudaEventDisableTiming);
        cudaFuncSetAttribute(flash_kernel,
                             cudaFuncAttributeMaxDynamicSharedMemorySize, FL_SMEM_BYTES);
        cudaFuncSetAttribute(gemm_f16<EPI_QKV>,
                             cudaFuncAttributeMaxDynamicSharedMemorySize, GEMM_SMEM);
        cudaFuncSetAttribute(gemm_f16<EPI_PROJ>,
                             cudaFuncAttributeMaxDynamicSharedMemorySize, GEMM_SMEM);
    }

    // fork
    cudaEventRecord(e_fork, 0);
    cudaStreamWaitEvent(s_bias, e_fork, 0);
    cudaStreamWaitEvent(s_cvt,  e_fork, 0);

    // side stream 1: bias gather (needed only by flash)
    bias16_kernel<<<dim3(N_ * N_ / 256, H_), 256, 0, s_bias>>>(att_bias, bias_idx, n_off);
    cudaEventRecord(e_bias, s_bias);

    // side stream 2: weight conversion (needed by QKV & proj GEMMs)
    cvt_kernel<<<16384, 256, 0, s_cvt>>>((const float4*)qkv_w, (const float4*)proj_w);
    cudaEventRecord(e_cvt, s_cvt);

    // main stream: LN (overlaps cvt + bias16)
    ln_kernel<<<ROWS_, 256>>>(x, ln_g, ln_b);

    // join cvt before QKV
    cudaStreamWaitEvent(0, e_cvt, 0);
    gemm_f16<EPI_QKV><<<dim3(QKV_OUT_ / 128, ROWS_ / 128), 256, GEMM_SMEM>>>(
        qkv_b, nullptr);

    // join bias before flash
    cudaStreamWaitEvent(0, e_bias, 0);
    flash_kernel<<<dim3(N_ / 128, BH_), 256, FL_SMEM_BYTES>>>();

    gemm_f16<EPI_PROJ><<<dim3(DIM_ / 128, ROWS_ / 128), 256, GEMM_SMEM>>>(
        proj_b, out);
}

// round 14
// speedup vs baseline: 1.0456x; 1.0025x over previous
#include <cuda_runtime.h>
#include <cuda_fp16.h>
#include <cstdint>

#define DEV_INLINE __device__ __forceinline__

// Problem constants
constexpr int B_    = 16;
constexpr int N_    = 1024;
constexpr int H_    = 16;
constexpr int D_    = 128;
constexpr int DIM_  = 2048;
constexpr int QKV_OUT_ = 6144;
constexpr int ROWS_ = B_ * N_;     // 16384
constexpr int BH_   = B_ * H_;     // 256
constexpr float LOG2E_ = 1.4426950408889634f;
constexpr float SCALE_ = 0.08838834764831845f;          // 128^-0.5
constexpr float QSC_   = SCALE_ * LOG2E_;               // q pre-scale, log2 domain
constexpr float LN_EPS_ = 1e-5f;

// ---------------- device scratch (static, no allocs) ----------------
__device__ __align__(16) __half g_xn  [(size_t)ROWS_ * DIM_];
__device__ __align__(16) __half g_wqkv[(size_t)DIM_ * QKV_OUT_];
__device__ __align__(16) __half g_wproj[(size_t)DIM_ * DIM_];
__device__ __align__(16) __half g_q   [(size_t)BH_ * N_ * D_];       // [bh][n][d], pre-scaled*log2e
__device__ __align__(16) __half g_k   [(size_t)BH_ * N_ * D_];       // [bh][n][d]
__device__ __align__(16) __half g_v   [(size_t)BH_ * N_ * D_];       // [bh][n][d]
__device__ __align__(16) __half g_bias16[(size_t)H_ * N_ * N_];      // gathered bias * log2e, fp16
__device__ __align__(16) __half g_ao  [(size_t)ROWS_ * DIM_];        // attn out [b,n,h*D+d]

// ---------------- helpers ----------------
DEV_INLINE uint32_t smem_u32(const void* p) {
    return (uint32_t)__cvta_generic_to_shared(p);
}
DEV_INLINE void cp16(void* s, const void* g) {
    asm volatile("cp.async.cg.shared.global [%0], [%1], 16;\n"
                 :: "r"(smem_u32(s)), "l"(g));
}
DEV_INLINE void cp_commit() { asm volatile("cp.async.commit_group;\n"); }
template <int n>
DEV_INLINE void cp_wait() { asm volatile("cp.async.wait_group %0;\n" :: "n"(n)); }

DEV_INLINE uint32_t h2_as_u32(__half2 h) {
    return *reinterpret_cast<uint32_t*>(&h);
}
DEV_INLINE float ex2f(float x) {
    float y;
    asm("ex2.approx.f32 %0, %1;" : "=f"(y) : "f"(x));
    return y;
}

DEV_INLINE void ldsm_x4(uint32_t& r0, uint32_t& r1, uint32_t& r2, uint32_t& r3, uint32_t a) {
    asm volatile("ldmatrix.sync.aligned.m8n8.x4.shared.b16 {%0,%1,%2,%3}, [%4];"
                 : "=r"(r0), "=r"(r1), "=r"(r2), "=r"(r3) : "r"(a));
}
DEV_INLINE void ldsm_x4_t(uint32_t& r0, uint32_t& r1, uint32_t& r2, uint32_t& r3, uint32_t a) {
    asm volatile("ldmatrix.sync.aligned.m8n8.x4.trans.shared.b16 {%0,%1,%2,%3}, [%4];"
                 : "=r"(r0), "=r"(r1), "=r"(r2), "=r"(r3) : "r"(a));
}
DEV_INLINE void mma16816(float* c, const uint32_t* a, const uint32_t* b) {
    asm volatile(
        "mma.sync.aligned.m16n8k16.row.col.f32.f16.f16.f32 "
        "{%0,%1,%2,%3}, {%4,%5,%6,%7}, {%8,%9}, {%0,%1,%2,%3};"
        : "+f"(c[0]), "+f"(c[1]), "+f"(c[2]), "+f"(c[3])
        : "r"(a[0]), "r"(a[1]), "r"(a[2]), "r"(a[3]), "r"(b[0]), "r"(b[1]));
}

DEV_INLINE float warp_sum(float v) {
    #pragma unroll
    for (int o = 16; o; o >>= 1) v += __shfl_xor_sync(0xFFFFFFFFu, v, o);
    return v;
}
DEV_INLINE float block_sum(float v, float* sred, int tid) {
    int lane = tid & 31, w = tid >> 5;
    v = warp_sum(v);
    if (lane == 0) sred[w] = v;
    __syncthreads();
    float r = sred[0];
    #pragma unroll
    for (int i = 1; i < 8; i++) r += sred[i];
    __syncthreads();
    return r;
}

// ---------------- weight fp32 -> fp16 conversion ----------------
__global__ void cvt_kernel(const float4* __restrict__ qkv_w, const float4* __restrict__ proj_w) {
    int i = blockIdx.x * blockDim.x + threadIdx.x;
    const int n1 = DIM_ * QKV_OUT_ / 4;
    const int n2 = DIM_ * DIM_ / 4;
    if (i < n1) {
        float4 v = qkv_w[i];
        __half2* dst = (__half2*)g_wqkv;
        dst[2 * i]     = __floats2half2_rn(v.x, v.y);
        dst[2 * i + 1] = __floats2half2_rn(v.z, v.w);
    } else if (i < n1 + n2) {
        int j = i - n1;
        float4 v = proj_w[j];
        __half2* dst = (__half2*)g_wproj;
        dst[2 * j]     = __floats2half2_rn(v.x, v.y);
        dst[2 * j + 1] = __floats2half2_rn(v.z, v.w);
    }
}

// ------- gather attention bias (scaled by log2e) to fp16 [h][i][j] -------
__global__ void bias16_kernel(const float* __restrict__ att_bias,
                              const int* __restrict__ idxs, int n_off) {
    int ij = blockIdx.x * 256 + threadIdx.x;
    int h  = blockIdx.y;
    g_bias16[(size_t)h * N_ * N_ + ij] =
        __float2half(att_bias[h * n_off + idxs[ij]] * LOG2E_);
}

// ---------------- LayerNorm ----------------
__global__ void ln_kernel(const float* __restrict__ x,
                          const float* __restrict__ gamma,
                          const float* __restrict__ beta) {
    __shared__ float sred[8];
    int row = blockIdx.x;
    int tid = threadIdx.x;
    const float4* x4 = (const float4*)(x + (size_t)row * DIM_);
    float4 v0 = x4[tid];
    float4 v1 = x4[tid + 256];

    float s = v0.x + v0.y + v0.z + v0.w + v1.x + v1.y + v1.z + v1.w;
    float q = v0.x*v0.x + v0.y*v0.y + v0.z*v0.z + v0.w*v0.w
            + v1.x*v1.x + v1.y*v1.y + v1.z*v1.z + v1.w*v1.w;

    float tot_s = block_sum(s, sred, tid);
    float tot_q = block_sum(q, sred, tid);
    float mean = tot_s * (1.0f / DIM_);
    float var  = tot_q * (1.0f / DIM_) - mean * mean;
    float rstd = rsqrtf(var + LN_EPS_);

    const float4* g4 = (const float4*)gamma;
    const float4* b4 = (const float4*)beta;
    float4 ga = g4[tid], gb = g4[tid + 256];
    float4 ba = b4[tid], bb = b4[tid + 256];

    __half2* o2 = (__half2*)(g_xn + (size_t)row * DIM_);
    o2[2 * tid]       = __floats2half2_rn((v0.x - mean) * rstd * ga.x + ba.x,
                                          (v0.y - mean) * rstd * ga.y + ba.y);
    o2[2 * tid + 1]   = __floats2half2_rn((v0.z - mean) * rstd * ga.z + ba.z,
                                          (v0.w - mean) * rstd * ga.w + ba.w);
    o2[512 + 2 * tid]     = __floats2half2_rn((v1.x - mean) * rstd * gb.x + bb.x,
                                              (v1.y - mean) * rstd * gb.y + bb.y);
    o2[512 + 2 * tid + 1] = __floats2half2_rn((v1.z - mean) * rstd * gb.z + bb.z,
                                              (v1.w - mean) * rstd * gb.w + bb.w);
}

// ------- dense GEMMs (QKV / proj): 4-stage cp.async, ldsm/mma pipelined -------
enum { EPI_QKV = 0, EPI_PROJ = 1 };

constexpr int AS_STAGE_B = 128 * 40 * 2;   // 10240
constexpr int BS_STAGE_B = 32 * 136 * 2;   //  8704
constexpr int AS_TOT_B   = 4 * AS_STAGE_B; // 40960
constexpr int GEMM_SMEM  = AS_TOT_B + 4 * BS_STAGE_B;  // 75776

template <int EPI>
__global__ void __launch_bounds__(256, 2)
gemm_f16(const float* __restrict__ bias, float* __restrict__ outf) {
    constexpr int K   = 2048;
    constexpr int LDA = 2048;
    constexpr int LDB = (EPI == EPI_QKV) ? 6144 : 2048;
    constexpr int NT  = K / 32;   // 64 k-tiles

    extern __shared__ __align__(16) char dynsm[];

    const int bm = blockIdx.y * 128;
    const int bn = blockIdx.x * 128;

    const __half* __restrict__ A  = (EPI == EPI_QKV) ? g_xn : g_ao;
    const __half* __restrict__ Bp = (EPI == EPI_QKV) ? g_wqkv : g_wproj;

    const int tid  = threadIdx.x;
    const int lane = tid & 31;
    const int warp = tid >> 5;
    const int wm = warp & 3;
    const int wn = warp >> 2;

    float acc[2][8][4];
    #pragma unroll
    for (int i = 0; i < 2; i++)
        #pragma unroll
        for (int j = 0; j < 8; j++)
            #pragma unroll
            for (int r = 0; r < 4; r++) acc[i][j][r] = 0.0f;

    auto As = [&](int s) -> __half (*)[40] {
        return reinterpret_cast<__half(*)[40]>(dynsm + s * AS_STAGE_B);
    };
    auto Bs = [&](int s) -> __half (*)[136] {
        return reinterpret_cast<__half(*)[136]>(dynsm + AS_TOT_B + s * BS_STAGE_B);
    };

    auto load_tile = [&](int s, int k0) {
        __half (*as)[40]  = As(s);
        __half (*bs)[136] = Bs(s);
        #pragma unroll
        for (int i = 0; i < 2; i++) {
            int lin = tid + i * 256;
            int m  = lin >> 2;
            int kq = (lin & 3) << 3;
            cp16(&as[m][kq], &A[(size_t)(bm + m) * LDA + k0 + kq]);
        }
        #pragma unroll
        for (int i = 0; i < 2; i++) {
            int lin = tid + i * 256;
            int kk = lin >> 4;
            int cq = (lin & 15) << 3;
            cp16(&bs[kk][cq], &Bp[(size_t)(k0 + kk) * LDB + bn + cq]);
        }
        cp_commit();
    };

    load_tile(0, 0);
    load_tile(1, 32);
    load_tile(2, 64);

    #pragma unroll 1
    for (int t = 0; t < NT; t++) {
        if (t <= NT - 3)      cp_wait<2>();
        else if (t == NT - 2) cp_wait<1>();
        else                  cp_wait<0>();
        __syncthreads();   // single barrier per iteration

        if (t + 3 < NT) load_tile((t + 3) & 3, (t + 3) * 32);

        const int s = t & 3;
        __half (*as)[40]  = As(s);
        __half (*bs)[136] = Bs(s);
        #pragma unroll
        for (int ks = 0; ks < 2; ks++) {
            uint32_t af[2][4];
            #pragma unroll
            for (int mf = 0; mf < 2; mf++) {
                uint32_t addr = smem_u32(
                    &as[wm * 32 + mf * 16 + (lane & 15)][ks * 16 + ((lane >> 4) << 3)]);
                ldsm_x4(af[mf][0], af[mf][1], af[mf][2], af[mf][3], addr);
            }
            // pipelined B-frag loads: ldsm for np+1 issues before mma of np
            uint32_t bbuf[2][4];
            {
                uint32_t addr = smem_u32(
                    &bs[ks * 16 + (lane & 15)][wn * 64 + 0 * 16 + ((lane >> 4) << 3)]);
                ldsm_x4_t(bbuf[0][0], bbuf[0][1], bbuf[0][2], bbuf[0][3], addr);
            }
            #pragma unroll
            for (int np = 0; np < 4; np++) {
                if (np < 3) {
                    uint32_t addr = smem_u32(
                        &bs[ks * 16 + (lane & 15)][wn * 64 + (np + 1) * 16 + ((lane >> 4) << 3)]);
                    ldsm_x4_t(bbuf[(np + 1) & 1][0], bbuf[(np + 1) & 1][1],
                              bbuf[(np + 1) & 1][2], bbuf[(np + 1) & 1][3], addr);
                }
                const uint32_t* bb = bbuf[np & 1];
                uint32_t bA[2] = {bb[0], bb[1]}, bB[2] = {bb[2], bb[3]};
                #pragma unroll
                for (int mf = 0; mf < 2; mf++) {
                    mma16816(acc[mf][np * 2],     af[mf], bA);
                    mma16816(acc[mf][np * 2 + 1], af[mf], bB);
                }
            }
        }
    }

    // epilogue
    const int g     = lane >> 2;
    const int cpair = (lane & 3) << 1;
    #pragma unroll
    for (int mf = 0; mf < 2; mf++)
        #pragma unroll
        for (int nf = 0; nf < 8; nf++) {
            int row0 = bm + wm * 32 + mf * 16 + g;
            int col  = bn + wn * 64 + nf * 8 + cpair;
            #pragma unroll
            for (int rr = 0; rr < 2; rr++) {
                int row = row0 + rr * 8;
                float v0 = acc[mf][nf][rr * 2];
                float v1 = acc[mf][nf][rr * 2 + 1];
                if constexpr (EPI == EPI_QKV) {
                    v0 += bias[col];
                    v1 += bias[col + 1];
                    int tsel = col >> 11;
                    int r = col & 2047;
                    int h = r >> 7, d = r & 127;
                    int b = row >> 10, n = row & 1023;
                    int bhi = (b << 4) + h;
                    size_t off = ((size_t)bhi * N_ + n) * D_ + d;
                    if (tsel == 0) {
                        *(__half2*)&g_q[off] = __floats2half2_rn(v0 * QSC_, v1 * QSC_);
                    } else if (tsel == 1) {
                        *(__half2*)&g_k[off] = __floats2half2_rn(v0, v1);
                    } else {
                        *(__half2*)&g_v[off] = __floats2half2_rn(v0, v1);
                    }
                } else {
                    float2 o;
                    o.x = v0 + bias[col];
                    o.y = v1 + bias[col + 1];
                    *(float2*)&outf[(size_t)row * DIM_ + col] = o;
                }
            }
        }
}

// ---------------- fused flash attention (log2 softmax, pipelined ldsm) ----------------
constexpr int FL_STRIDE = 136;
constexpr int FL_TILE   = 128 * FL_STRIDE;
constexpr int FL_STAGE  = 3 * FL_TILE;               // K + V + bias
constexpr int FL_SMEM_BYTES = 2 * FL_STAGE * 2;      // 208896

__global__ void __launch_bounds__(256, 1)
flash_kernel() {
    extern __shared__ char g_smem[];
    __half* sm = (__half*)g_smem;

    const int tid  = threadIdx.x;
    const int lane = tid & 31;
    const int w    = tid >> 5;
    const int qt   = blockIdx.x;
    const int bh   = blockIdx.y;
    const int h    = bh & 15;
    const int b    = bh >> 4;

    const __half* __restrict__ Qp = g_q + ((size_t)bh * N_ + qt * 128) * D_;
    const __half* __restrict__ Kp = g_k + (size_t)bh * N_ * D_;
    const __half* __restrict__ Vp = g_v + (size_t)bh * N_ * D_;
    const __half* __restrict__ Bb = g_bias16 + (size_t)h * N_ * N_ + (size_t)(qt * 128) * N_;

    // ---- stage Q through smem, extract register fragments ----
    {
        __half* sQ = sm;
        #pragma unroll
        for (int i = 0; i < 8; i++) {
            int chunk = tid + i * 256;
            int r  = chunk >> 4;
            int c8 = (chunk & 15) << 3;
            *(float4*)&sQ[r * FL_STRIDE + c8] = *(const float4*)&Qp[r * D_ + c8];
        }
    }
    __syncthreads();
    uint32_t aq[8][4];
    #pragma unroll
    for (int kc = 0; kc < 8; kc++) {
        uint32_t addr = smem_u32(
            &sm[(w * 16 + (lane & 15)) * FL_STRIDE + kc * 16 + ((lane >> 4) << 3)]);
        ldsm_x4(aq[kc][0], aq[kc][1], aq[kc][2], aq[kc][3], addr);
    }
    __syncthreads();

    auto load_kv = [&](int s, int jt) {
        __half* sK = sm + s * FL_STAGE;
        __half* sV = sK + FL_TILE;
        __half* sB = sV + FL_TILE;
        #pragma unroll
        for (int i = 0; i < 8; i++) {
            int chunk = tid + i * 256;
            int r  = chunk >> 4;
            int c8 = (chunk & 15) << 3;
            cp16(&sK[r * FL_STRIDE + c8], &Kp[(size_t)(jt * 128 + r) * D_ + c8]);
        }
        #pragma unroll
        for (int i = 0; i < 8; i++) {
            int chunk = tid + i * 256;
            int r  = chunk >> 4;
            int c8 = (chunk & 15) << 3;
            cp16(&sV[r * FL_STRIDE + c8], &Vp[(size_t)(jt * 128 + r) * D_ + c8]);
        }
        #pragma unroll
        for (int i = 0; i < 8; i++) {
            int chunk = tid + i * 256;
            int r  = chunk >> 4;
            int c8 = (chunk & 15) << 3;
            cp16(&sB[r * FL_STRIDE + c8], &Bb[(size_t)r * N_ + jt * 128 + c8]);
        }
        cp_commit();
    };

    float acc_o[16][4];
    #pragma unroll
    for (int i = 0; i < 16; i++)
        #pragma unroll
        for (int r = 0; r < 4; r++) acc_o[i][r] = 0.0f;
    float m0 = -1e30f, m1 = -1e30f, l0 = 0.0f, l1 = 0.0f;

    const int g = lane >> 2;

    load_kv(0, 0);

    #pragma unroll 1
    for (int jt = 0; jt < 8; jt++) {
        if (jt + 1 < 8) { load_kv((jt + 1) & 1, jt + 1); cp_wait<1>(); }
        else            { cp_wait<0>(); }
        __syncthreads();

        const __half* sK = sm + (jt & 1) * FL_STAGE;
        const __half* sV = sK + FL_TILE;
        const __half* sB = sV + FL_TILE;

        // ---- S = Q K^T (16 x 128 per warp), pipelined K-frag loads ----
        float accs[16][4];
        #pragma unroll
        for (int i = 0; i < 16; i++)
            #pragma unroll
            for (int r = 0; r < 4; r++) accs[i][r] = 0.0f;

        #pragma unroll
        for (int kc = 0; kc < 8; kc++) {
            uint32_t kbuf[2][4];
            {
                uint32_t addr = smem_u32(
                    &sK[(0 * 16 + (lane & 15)) * FL_STRIDE + kc * 16 + ((lane >> 4) << 3)]);
                ldsm_x4(kbuf[0][0], kbuf[0][1], kbuf[0][2], kbuf[0][3], addr);
            }
            #pragma unroll
            for (int nf2 = 0; nf2 < 8; nf2++) {
                if (nf2 < 7) {
                    uint32_t addr = smem_u32(
                        &sK[((nf2 + 1) * 16 + (lane & 15)) * FL_STRIDE + kc * 16 + ((lane >> 4) << 3)]);
                    ldsm_x4(kbuf[(nf2 + 1) & 1][0], kbuf[(nf2 + 1) & 1][1],
                            kbuf[(nf2 + 1) & 1][2], kbuf[(nf2 + 1) & 1][3], addr);
                }
                const uint32_t* kb = kbuf[nf2 & 1];
                uint32_t bA[2] = {kb[0], kb[2]}, bB[2] = {kb[1], kb[3]};
                mma16816(accs[nf2 * 2],     aq[kc], bA);
                mma16816(accs[nf2 * 2 + 1], aq[kc], bB);
            }
        }

        // ---- bias add (from smem) + online softmax (base-2) ----
        const int cpair = (lane & 3) << 1;
        const __half* srow0 = sB + (size_t)(w * 16 + g) * FL_STRIDE;
        const __half* srow1 = srow0 + 8 * FL_STRIDE;
        float mx0 = -1e30f, mx1 = -1e30f;
        #pragma unroll
        for (int nf = 0; nf < 16; nf++) {
            int col = nf * 8 + cpair;
            __half2 b0 = *(const __half2*)&srow0[col];
            __half2 b1 = *(const __half2*)&srow1[col];
            accs[nf][0] += __low2float(b0);
            accs[nf][1] += __high2float(b0);
            accs[nf][2] += __low2float(b1);
            accs[nf][3] += __high2float(b1);
            mx0 = fmaxf(mx0, fmaxf(accs[nf][0], accs[nf][1]));
            mx1 = fmaxf(mx1, fmaxf(accs[nf][2], accs[nf][3]));
        }
        mx0 = fmaxf(mx0, __shfl_xor_sync(0xFFFFFFFFu, mx0, 1));
        mx0 = fmaxf(mx0, __shfl_xor_sync(0xFFFFFFFFu, mx0, 2));
        mx1 = fmaxf(mx1, __shfl_xor_sync(0xFFFFFFFFu, mx1, 1));
        mx1 = fmaxf(mx1, __shfl_xor_sync(0xFFFFFFFFu, mx1, 2));

        float mn0 = fmaxf(m0, mx0), mn1 = fmaxf(m1, mx1);
        float sc0 = ex2f(m0 - mn0), sc1 = ex2f(m1 - mn1);
        m0 = mn0; m1 = mn1;

        float sum0 = 0.0f, sum1 = 0.0f;
        uint32_t ph[8][4];
        #pragma unroll
        for (int nf = 0; nf < 16; nf++) {
            float p0 = ex2f(accs[nf][0] - m0);
            float p1 = ex2f(accs[nf][1] - m0);
            float p2 = ex2f(accs[nf][2] - m1);
            float p3 = ex2f(accs[nf][3] - m1);
            sum0 += p0 + p1;
            sum1 += p2 + p3;
            uint32_t lo = h2_as_u32(__floats2half2_rn(p0, p1));
            uint32_t hi = h2_as_u32(__floats2half2_rn(p2, p3));
            int kc = nf >> 1;
            if ((nf & 1) == 0) { ph[kc][0] = lo; ph[kc][1] = hi; }
            else               { ph[kc][2] = lo; ph[kc][3] = hi; }
        }
        sum0 += __shfl_xor_sync(0xFFFFFFFFu, sum0, 1);
        sum0 += __shfl_xor_sync(0xFFFFFFFFu, sum0, 2);
        sum1 += __shfl_xor_sync(0xFFFFFFFFu, sum1, 1);
        sum1 += __shfl_xor_sync(0xFFFFFFFFu, sum1, 2);
        l0 = l0 * sc0 + sum0;
        l1 = l1 * sc1 + sum1;

        #pragma unroll
        for (int nf = 0; nf < 16; nf++) {
            acc_o[nf][0] *= sc0; acc_o[nf][1] *= sc0;
            acc_o[nf][2] *= sc1; acc_o[nf][3] *= sc1;
        }

        // ---- O += P V, pipelined V-frag loads ----
        #pragma unroll
        for (int kc = 0; kc < 8; kc++) {
            uint32_t vbuf[2][4];
            {
                uint32_t addr = smem_u32(
                    &sV[(kc * 16 + (lane & 15)) * FL_STRIDE + 0 * 16 + ((lane >> 4) << 3)]);
                ldsm_x4_t(vbuf[0][0], vbuf[0][1], vbuf[0][2], vbuf[0][3], addr);
            }
            #pragma unroll
            for (int nf2 = 0; nf2 < 8; nf2++) {
                if (nf2 < 7) {
                    uint32_t addr = smem_u32(
                        &sV[(kc * 16 + (lane & 15)) * FL_STRIDE + (nf2 + 1) * 16 + ((lane >> 4) << 3)]);
                    ldsm_x4_t(vbuf[(nf2 + 1) & 1][0], vbuf[(nf2 + 1) & 1][1],
                              vbuf[(nf2 + 1) & 1][2], vbuf[(nf2 + 1) & 1][3], addr);
                }
                const uint32_t* vb = vbuf[nf2 & 1];
                uint32_t bA[2] = {vb[0], vb[1]}, bB[2] = {vb[2], vb[3]};
                mma16816(acc_o[nf2 * 2],     ph[kc], bA);
                mma16816(acc_o[nf2 * 2 + 1], ph[kc], bB);
            }
        }
        __syncthreads();
    }

    // ---- normalize + write [b, n, h*128+d] ----
    float inv0 = __frcp_rn(l0), inv1 = __frcp_rn(l1);
    const int cpair = (lane & 3) << 1;
    int n0 = qt * 128 + w * 16 + g;
    __half* dst0 = g_ao + ((size_t)(b * N_ + n0)) * DIM_ + h * D_;
    __half* dst1 = dst0 + (size_t)8 * DIM_;
    #pragma unroll
    for (int nf = 0; nf < 16; nf++) {
        int col = nf * 8 + cpair;
        *(__half2*)&dst0[col] = __floats2half2_rn(acc_o[nf][0] * inv0, acc_o[nf][1] * inv0);
        *(__half2*)&dst1[col] = __floats2half2_rn(acc_o[nf][2] * inv1, acc_o[nf][3] * inv1);
    }
}

// ---------------- launch (stream fork/join for independent prologue) ----------------
extern "C" void kernel_launch(void* const* d_in, const int* in_sizes, int n_in,
                              void* d_out, int out_size) {
    const float* x        = (const float*)d_in[0];
    const float* ln_g     = (const float*)d_in[1];
    const float* ln_b     = (const float*)d_in[2];
    const float* qkv_w    = (const float*)d_in[3];
    const float* qkv_b    = (const float*)d_in[4];
    const float* proj_w   = (const float*)d_in[5];
    const float* proj_b   = (const float*)d_in[6];
    const float* att_bias = (const float*)d_in[7];
    const int*   bias_idx = (const int*)d_in[8];
    float* out = (float*)d_out;

    int n_off = in_sizes[7] / H_;   // 1024

    static bool inited = false;
    static cudaStream_t s_bias, s_cvt;
    static cudaEvent_t e_fork, e_bias, e_cvt;
    if (!inited) {
        inited = true;
        cudaStreamCreateWithFlags(&s_bias, cudaStreamNonBlocking);
        cudaStreamCreateWithFlags(&s_cvt,  cudaStreamNonBlocking);
        cudaEventCreateWithFlags(&e_fork, cudaEventDisableTiming);
        cudaEventCreateWithFlags(&e_bias, cudaEventDisableTiming);
        cudaEventCreateWithFlags(&e_cvt,  cudaEventDisableTiming);
        cudaFuncSetAttribute(flash_kernel,
                             cudaFuncAttributeMaxDynamicSharedMemorySize, FL_SMEM_BYTES);
        cudaFuncSetAttribute(gemm_f16<EPI_QKV>,
                             cudaFuncAttributeMaxDynamicSharedMemorySize, GEMM_SMEM);
        cudaFuncSetAttribute(gemm_f16<EPI_PROJ>,
                             cudaFuncAttributeMaxDynamicSharedMemorySize, GEMM_SMEM);
    }

    // fork
    cudaEventRecord(e_fork, 0);
    cudaStreamWaitEvent(s_bias, e_fork, 0);
    cudaStreamWaitEvent(s_cvt,  e_fork, 0);

    bias16_kernel<<<dim3(N_ * N_ / 256, H_), 256, 0, s_bias>>>(att_bias, bias_idx, n_off);
    cudaEventRecord(e_bias, s_bias);

    cvt_kernel<<<16384, 256, 0, s_cvt>>>((const float4*)qkv_w, (const float4*)proj_w);
    cudaEventRecord(e_cvt, s_cvt);

    ln_kernel<<<ROWS_, 256>>>(x, ln_g, ln_b);

    cudaStreamWaitEvent(0, e_cvt, 0);
    gemm_f16<EPI_QKV><<<dim3(QKV_OUT_ / 128, ROWS_ / 128), 256, GEMM_SMEM>>>(
        qkv_b, nullptr);

    cudaStreamWaitEvent(0, e_bias, 0);
    flash_kernel<<<dim3(N_ / 128, BH_), 256, FL_SMEM_BYTES>>>();

    gemm_f16<EPI_PROJ><<<dim3(DIM_ / 128, ROWS_ / 128), 256, GEMM_SMEM>>>(
        proj_b, out);
}

// round 15
// speedup vs baseline: 1.0510x; 1.0052x over previous
#include <cuda_runtime.h>
#include <cuda_fp16.h>
#include <cstdint>

#define DEV_INLINE __device__ __forceinline__

// Problem constants
constexpr int B_    = 16;
constexpr int N_    = 1024;
constexpr int H_    = 16;
constexpr int D_    = 128;
constexpr int DIM_  = 2048;
constexpr int QKV_OUT_ = 6144;
constexpr int ROWS_ = B_ * N_;     // 16384
constexpr int BH_   = B_ * H_;     // 256
constexpr float LOG2E_ = 1.4426950408889634f;
constexpr float SCALE_ = 0.08838834764831845f;          // 128^-0.5
constexpr float QSC_   = SCALE_ * LOG2E_;               // q pre-scale, log2 domain
constexpr float LN_EPS_ = 1e-5f;

// ---------------- device scratch (static, no allocs) ----------------
__device__ __align__(16) __half g_xn  [(size_t)ROWS_ * DIM_];
__device__ __align__(16) __half g_wqkv[(size_t)DIM_ * QKV_OUT_];
__device__ __align__(16) __half g_wproj[(size_t)DIM_ * DIM_];
__device__ __align__(16) __half g_q   [(size_t)BH_ * N_ * D_];       // [bh][n][d], pre-scaled*log2e
__device__ __align__(16) __half g_k   [(size_t)BH_ * N_ * D_];       // [bh][n][d]
__device__ __align__(16) __half g_v   [(size_t)BH_ * N_ * D_];       // [bh][n][d]
__device__ __align__(16) __half g_bias16[(size_t)H_ * N_ * N_];      // gathered bias * log2e, fp16
__device__ __align__(16) __half g_ao  [(size_t)ROWS_ * DIM_];        // attn out [b,n,h*D+d]

// ---------------- helpers ----------------
DEV_INLINE uint32_t smem_u32(const void* p) {
    return (uint32_t)__cvta_generic_to_shared(p);
}
DEV_INLINE void cp16(void* s, const void* g) {
    asm volatile("cp.async.cg.shared.global [%0], [%1], 16;\n"
                 :: "r"(smem_u32(s)), "l"(g));
}
DEV_INLINE void cp_commit() { asm volatile("cp.async.commit_group;\n"); }
template <int n>
DEV_INLINE void cp_wait() { asm volatile("cp.async.wait_group %0;\n" :: "n"(n)); }

DEV_INLINE uint32_t h2_as_u32(__half2 h) {
    return *reinterpret_cast<uint32_t*>(&h);
}
DEV_INLINE float ex2f(float x) {
    float y;
    asm("ex2.approx.f32 %0, %1;" : "=f"(y) : "f"(x));
    return y;
}

DEV_INLINE void ldsm_x4(uint32_t& r0, uint32_t& r1, uint32_t& r2, uint32_t& r3, uint32_t a) {
    asm volatile("ldmatrix.sync.aligned.m8n8.x4.shared.b16 {%0,%1,%2,%3}, [%4];"
                 : "=r"(r0), "=r"(r1), "=r"(r2), "=r"(r3) : "r"(a));
}
DEV_INLINE void ldsm_x4_t(uint32_t& r0, uint32_t& r1, uint32_t& r2, uint32_t& r3, uint32_t a) {
    asm volatile("ldmatrix.sync.aligned.m8n8.x4.trans.shared.b16 {%0,%1,%2,%3}, [%4];"
                 : "=r"(r0), "=r"(r1), "=r"(r2), "=r"(r3) : "r"(a));
}
DEV_INLINE void mma16816(float* c, const uint32_t* a, const uint32_t* b) {
    asm volatile(
        "mma.sync.aligned.m16n8k16.row.col.f32.f16.f16.f32 "
        "{%0,%1,%2,%3}, {%4,%5,%6,%7}, {%8,%9}, {%0,%1,%2,%3};"
        : "+f"(c[0]), "+f"(c[1]), "+f"(c[2]), "+f"(c[3])
        : "r"(a[0]), "r"(a[1]), "r"(a[2]), "r"(a[3]), "r"(b[0]), "r"(b[1]));
}

DEV_INLINE float warp_sum(float v) {
    #pragma unroll
    for (int o = 16; o; o >>= 1) v += __shfl_xor_sync(0xFFFFFFFFu, v, o);
    return v;
}
DEV_INLINE float block_sum(float v, float* sred, int tid) {
    int lane = tid & 31, w = tid >> 5;
    v = warp_sum(v);
    if (lane == 0) sred[w] = v;
    __syncthreads();
    float r = sred[0];
    #pragma unroll
    for (int i = 1; i < 8; i++) r += sred[i];
    __syncthreads();
    return r;
}

// ---------------- weight fp32 -> fp16 conversion ----------------
__global__ void cvt_kernel(const float4* __restrict__ qkv_w, const float4* __restrict__ proj_w) {
    int i = blockIdx.x * blockDim.x + threadIdx.x;
    const int n1 = DIM_ * QKV_OUT_ / 4;
    const int n2 = DIM_ * DIM_ / 4;
    if (i < n1) {
        float4 v = qkv_w[i];
        __half2* dst = (__half2*)g_wqkv;
        dst[2 * i]     = __floats2half2_rn(v.x, v.y);
        dst[2 * i + 1] = __floats2half2_rn(v.z, v.w);
    } else if (i < n1 + n2) {
        int j = i - n1;
        float4 v = proj_w[j];
        __half2* dst = (__half2*)g_wproj;
        dst[2 * j]     = __floats2half2_rn(v.x, v.y);
        dst[2 * j + 1] = __floats2half2_rn(v.z, v.w);
    }
}

// ------- gather attention bias (scaled by log2e) to fp16 [h][i][j] -------
__global__ void bias16_kernel(const float* __restrict__ att_bias,
                              const int* __restrict__ idxs, int n_off) {
    int ij = blockIdx.x * 256 + threadIdx.x;
    int h  = blockIdx.y;
    g_bias16[(size_t)h * N_ * N_ + ij] =
        __float2half(att_bias[h * n_off + idxs[ij]] * LOG2E_);
}

// ---------------- LayerNorm ----------------
__global__ void ln_kernel(const float* __restrict__ x,
                          const float* __restrict__ gamma,
                          const float* __restrict__ beta) {
    __shared__ float sred[8];
    int row = blockIdx.x;
    int tid = threadIdx.x;
    const float4* x4 = (const float4*)(x + (size_t)row * DIM_);
    float4 v0 = x4[tid];
    float4 v1 = x4[tid + 256];

    float s = v0.x + v0.y + v0.z + v0.w + v1.x + v1.y + v1.z + v1.w;
    float q = v0.x*v0.x + v0.y*v0.y + v0.z*v0.z + v0.w*v0.w
            + v1.x*v1.x + v1.y*v1.y + v1.z*v1.z + v1.w*v1.w;

    float tot_s = block_sum(s, sred, tid);
    float tot_q = block_sum(q, sred, tid);
    float mean = tot_s * (1.0f / DIM_);
    float var  = tot_q * (1.0f / DIM_) - mean * mean;
    float rstd = rsqrtf(var + LN_EPS_);

    const float4* g4 = (const float4*)gamma;
    const float4* b4 = (const float4*)beta;
    float4 ga = g4[tid], gb = g4[tid + 256];
    float4 ba = b4[tid], bb = b4[tid + 256];

    __half2* o2 = (__half2*)(g_xn + (size_t)row * DIM_);
    o2[2 * tid]       = __floats2half2_rn((v0.x - mean) * rstd * ga.x + ba.x,
                                          (v0.y - mean) * rstd * ga.y + ba.y);
    o2[2 * tid + 1]   = __floats2half2_rn((v0.z - mean) * rstd * ga.z + ba.z,
                                          (v0.w - mean) * rstd * ga.w + ba.w);
    o2[512 + 2 * tid]     = __floats2half2_rn((v1.x - mean) * rstd * gb.x + bb.x,
                                              (v1.y - mean) * rstd * gb.y + bb.y);
    o2[512 + 2 * tid + 1] = __floats2half2_rn((v1.z - mean) * rstd * gb.z + bb.z,
                                              (v1.w - mean) * rstd * gb.w + bb.w);
}

// ------- dense GEMMs (QKV / proj): 4-stage cp.async, ONE barrier/iter (R12) -------
enum { EPI_QKV = 0, EPI_PROJ = 1 };

constexpr int AS_STAGE_B = 128 * 40 * 2;   // 10240
constexpr int BS_STAGE_B = 32 * 136 * 2;   //  8704
constexpr int AS_TOT_B   = 4 * AS_STAGE_B; // 40960
constexpr int GEMM_SMEM  = AS_TOT_B + 4 * BS_STAGE_B;  // 75776

template <int EPI>
__global__ void __launch_bounds__(256, 2)
gemm_f16(const float* __restrict__ bias, float* __restrict__ outf) {
    constexpr int K   = 2048;
    constexpr int LDA = 2048;
    constexpr int LDB = (EPI == EPI_QKV) ? 6144 : 2048;
    constexpr int NT  = K / 32;   // 64 k-tiles

    extern __shared__ __align__(16) char dynsm[];

    const int bm = blockIdx.y * 128;
    const int bn = blockIdx.x * 128;

    const __half* __restrict__ A  = (EPI == EPI_QKV) ? g_xn : g_ao;
    const __half* __restrict__ Bp = (EPI == EPI_QKV) ? g_wqkv : g_wproj;

    const int tid  = threadIdx.x;
    const int lane = tid & 31;
    const int warp = tid >> 5;
    const int wm = warp & 3;
    const int wn = warp >> 2;

    float acc[2][8][4];
    #pragma unroll
    for (int i = 0; i < 2; i++)
        #pragma unroll
        for (int j = 0; j < 8; j++)
            #pragma unroll
            for (int r = 0; r < 4; r++) acc[i][j][r] = 0.0f;

    auto As = [&](int s) -> __half (*)[40] {
        return reinterpret_cast<__half(*)[40]>(dynsm + s * AS_STAGE_B);
    };
    auto Bs = [&](int s) -> __half (*)[136] {
        return reinterpret_cast<__half(*)[136]>(dynsm + AS_TOT_B + s * BS_STAGE_B);
    };

    auto load_tile = [&](int s, int k0) {
        __half (*as)[40]  = As(s);
        __half (*bs)[136] = Bs(s);
        #pragma unroll
        for (int i = 0; i < 2; i++) {
            int lin = tid + i * 256;
            int m  = lin >> 2;
            int kq = (lin & 3) << 3;
            cp16(&as[m][kq], &A[(size_t)(bm + m) * LDA + k0 + kq]);
        }
        #pragma unroll
        for (int i = 0; i < 2; i++) {
            int lin = tid + i * 256;
            int kk = lin >> 4;
            int cq = (lin & 15) << 3;
            cp16(&bs[kk][cq], &Bp[(size_t)(k0 + kk) * LDB + bn + cq]);
        }
        cp_commit();
    };

    load_tile(0, 0);
    load_tile(1, 32);
    load_tile(2, 64);

    #pragma unroll 1
    for (int t = 0; t < NT; t++) {
        if (t <= NT - 3)      cp_wait<2>();
        else if (t == NT - 2) cp_wait<1>();
        else                  cp_wait<0>();
        __syncthreads();   // single barrier per iteration

        if (t + 3 < NT) load_tile((t + 3) & 3, (t + 3) * 32);

        const int s = t & 3;
        __half (*as)[40]  = As(s);
        __half (*bs)[136] = Bs(s);
        #pragma unroll
        for (int ks = 0; ks < 2; ks++) {
            uint32_t af[2][4];
            #pragma unroll
            for (int mf = 0; mf < 2; mf++) {
                uint32_t addr = smem_u32(
                    &as[wm * 32 + mf * 16 + (lane & 15)][ks * 16 + ((lane >> 4) << 3)]);
                ldsm_x4(af[mf][0], af[mf][1], af[mf][2], af[mf][3], addr);
            }
            uint32_t bf[8][2];
            #pragma unroll
            for (int np = 0; np < 4; np++) {
                uint32_t addr = smem_u32(
                    &bs[ks * 16 + (lane & 15)][wn * 64 + np * 16 + ((lane >> 4) << 3)]);
                uint32_t r0, r1, r2, r3;
                ldsm_x4_t(r0, r1, r2, r3, addr);
                bf[np * 2][0] = r0;     bf[np * 2][1] = r1;
                bf[np * 2 + 1][0] = r2; bf[np * 2 + 1][1] = r3;
            }
            #pragma unroll
            for (int mf = 0; mf < 2; mf++)
                #pragma unroll
                for (int nf = 0; nf < 8; nf++)
                    mma16816(acc[mf][nf], af[mf], bf[nf]);
        }
    }

    // epilogue
    const int g     = lane >> 2;
    const int cpair = (lane & 3) << 1;
    #pragma unroll
    for (int mf = 0; mf < 2; mf++)
        #pragma unroll
        for (int nf = 0; nf < 8; nf++) {
            int row0 = bm + wm * 32 + mf * 16 + g;
            int col  = bn + wn * 64 + nf * 8 + cpair;
            #pragma unroll
            for (int rr = 0; rr < 2; rr++) {
                int row = row0 + rr * 8;
                float v0 = acc[mf][nf][rr * 2];
                float v1 = acc[mf][nf][rr * 2 + 1];
                if constexpr (EPI == EPI_QKV) {
                    v0 += bias[col];
                    v1 += bias[col + 1];
                    int tsel = col >> 11;
                    int r = col & 2047;
                    int h = r >> 7, d = r & 127;
                    int b = row >> 10, n = row & 1023;
                    int bhi = (b << 4) + h;
                    size_t off = ((size_t)bhi * N_ + n) * D_ + d;
                    if (tsel == 0) {
                        *(__half2*)&g_q[off] = __floats2half2_rn(v0 * QSC_, v1 * QSC_);
                    } else if (tsel == 1) {
                        *(__half2*)&g_k[off] = __floats2half2_rn(v0, v1);
                    } else {
                        *(__half2*)&g_v[off] = __floats2half2_rn(v0, v1);
                    }
                } else {
                    float2 o;
                    o.x = v0 + bias[col];
                    o.y = v1 + bias[col + 1];
                    *(float2*)&outf[(size_t)row * DIM_ + col] = o;
                }
            }
        }
}

// ------- fused flash attention (log2 softmax, bias-seeded accumulators) -------
constexpr int FL_STRIDE = 136;
constexpr int FL_TILE   = 128 * FL_STRIDE;
constexpr int FL_STAGE  = 3 * FL_TILE;               // K + V + bias
constexpr int FL_SMEM_BYTES = 2 * FL_STAGE * 2;      // 208896

__global__ void __launch_bounds__(256, 1)
flash_kernel() {
    extern __shared__ char g_smem[];
    __half* sm = (__half*)g_smem;

    const int tid  = threadIdx.x;
    const int lane = tid & 31;
    const int w    = tid >> 5;
    const int qt   = blockIdx.x;
    const int bh   = blockIdx.y;
    const int h    = bh & 15;
    const int b    = bh >> 4;

    const __half* __restrict__ Qp = g_q + ((size_t)bh * N_ + qt * 128) * D_;
    const __half* __restrict__ Kp = g_k + (size_t)bh * N_ * D_;
    const __half* __restrict__ Vp = g_v + (size_t)bh * N_ * D_;
    const __half* __restrict__ Bb = g_bias16 + (size_t)h * N_ * N_ + (size_t)(qt * 128) * N_;

    // ---- stage Q through smem, extract register fragments ----
    {
        __half* sQ = sm;
        #pragma unroll
        for (int i = 0; i < 8; i++) {
            int chunk = tid + i * 256;
            int r  = chunk >> 4;
            int c8 = (chunk & 15) << 3;
            *(float4*)&sQ[r * FL_STRIDE + c8] = *(const float4*)&Qp[r * D_ + c8];
        }
    }
    __syncthreads();
    uint32_t aq[8][4];
    #pragma unroll
    for (int kc = 0; kc < 8; kc++) {
        uint32_t addr = smem_u32(
            &sm[(w * 16 + (lane & 15)) * FL_STRIDE + kc * 16 + ((lane >> 4) << 3)]);
        ldsm_x4(aq[kc][0], aq[kc][1], aq[kc][2], aq[kc][3], addr);
    }
    __syncthreads();

    auto load_kv = [&](int s, int jt) {
        __half* sK = sm + s * FL_STAGE;
        __half* sV = sK + FL_TILE;
        __half* sB = sV + FL_TILE;
        #pragma unroll
        for (int i = 0; i < 8; i++) {
            int chunk = tid + i * 256;
            int r  = chunk >> 4;
            int c8 = (chunk & 15) << 3;
            cp16(&sK[r * FL_STRIDE + c8], &Kp[(size_t)(jt * 128 + r) * D_ + c8]);
        }
        #pragma unroll
        for (int i = 0; i < 8; i++) {
            int chunk = tid + i * 256;
            int r  = chunk >> 4;
            int c8 = (chunk & 15) << 3;
            cp16(&sV[r * FL_STRIDE + c8], &Vp[(size_t)(jt * 128 + r) * D_ + c8]);
        }
        #pragma unroll
        for (int i = 0; i < 8; i++) {
            int chunk = tid + i * 256;
            int r  = chunk >> 4;
            int c8 = (chunk & 15) << 3;
            cp16(&sB[r * FL_STRIDE + c8], &Bb[(size_t)r * N_ + jt * 128 + c8]);
        }
        cp_commit();
    };

    float acc_o[16][4];
    #pragma unroll
    for (int i = 0; i < 16; i++)
        #pragma unroll
        for (int r = 0; r < 4; r++) acc_o[i][r] = 0.0f;
    float m0 = -1e30f, m1 = -1e30f, l0 = 0.0f, l1 = 0.0f;

    const int g = lane >> 2;
    const int cpair = (lane & 3) << 1;

    load_kv(0, 0);

    #pragma unroll 1
    for (int jt = 0; jt < 8; jt++) {
        if (jt + 1 < 8) { load_kv((jt + 1) & 1, jt + 1); cp_wait<1>(); }
        else            { cp_wait<0>(); }
        __syncthreads();

        const __half* sK = sm + (jt & 1) * FL_STAGE;
        const __half* sV = sK + FL_TILE;
        const __half* sB = sV + FL_TILE;

        // ---- seed S accumulators with bias fragments (C init = bias) ----
        const __half* srow0 = sB + (size_t)(w * 16 + g) * FL_STRIDE;
        const __half* srow1 = srow0 + 8 * FL_STRIDE;
        float accs[16][4];
        #pragma unroll
        for (int nf = 0; nf < 16; nf++) {
            int col = nf * 8 + cpair;
            __half2 b0 = *(const __half2*)&srow0[col];
            __half2 b1 = *(const __half2*)&srow1[col];
            accs[nf][0] = __low2float(b0);
            accs[nf][1] = __high2float(b0);
            accs[nf][2] = __low2float(b1);
            accs[nf][3] = __high2float(b1);
        }

        // ---- S = bias + Q K^T (16 x 128 per warp), pipelined K-frag loads ----
        #pragma unroll
        for (int kc = 0; kc < 8; kc++) {
            uint32_t kbuf[2][4];
            {
                uint32_t addr = smem_u32(
                    &sK[(0 * 16 + (lane & 15)) * FL_STRIDE + kc * 16 + ((lane >> 4) << 3)]);
                ldsm_x4(kbuf[0][0], kbuf[0][1], kbuf[0][2], kbuf[0][3], addr);
            }
            #pragma unroll
            for (int nf2 = 0; nf2 < 8; nf2++) {
                if (nf2 < 7) {
                    uint32_t addr = smem_u32(
                        &sK[((nf2 + 1) * 16 + (lane & 15)) * FL_STRIDE + kc * 16 + ((lane >> 4) << 3)]);
                    ldsm_x4(kbuf[(nf2 + 1) & 1][0], kbuf[(nf2 + 1) & 1][1],
                            kbuf[(nf2 + 1) & 1][2], kbuf[(nf2 + 1) & 1][3], addr);
                }
                const uint32_t* kb = kbuf[nf2 & 1];
                uint32_t bA[2] = {kb[0], kb[2]}, bB[2] = {kb[1], kb[3]};
                mma16816(accs[nf2 * 2],     aq[kc], bA);
                mma16816(accs[nf2 * 2 + 1], aq[kc], bB);
            }
        }

        // ---- online softmax (base-2), bias already folded in ----
        float mx0 = -1e30f, mx1 = -1e30f;
        #pragma unroll
        for (int nf = 0; nf < 16; nf++) {
            mx0 = fmaxf(mx0, fmaxf(accs[nf][0], accs[nf][1]));
            mx1 = fmaxf(mx1, fmaxf(accs[nf][2], accs[nf][3]));
        }
        mx0 = fmaxf(mx0, __shfl_xor_sync(0xFFFFFFFFu, mx0, 1));
        mx0 = fmaxf(mx0, __shfl_xor_sync(0xFFFFFFFFu, mx0, 2));
        mx1 = fmaxf(mx1, __shfl_xor_sync(0xFFFFFFFFu, mx1, 1));
        mx1 = fmaxf(mx1, __shfl_xor_sync(0xFFFFFFFFu, mx1, 2));

        float mn0 = fmaxf(m0, mx0), mn1 = fmaxf(m1, mx1);
        float sc0 = ex2f(m0 - mn0), sc1 = ex2f(m1 - mn1);
        m0 = mn0; m1 = mn1;

        float sum0 = 0.0f, sum1 = 0.0f;
        uint32_t ph[8][4];
        #pragma unroll
        for (int nf = 0; nf < 16; nf++) {
            float p0 = ex2f(accs[nf][0] - m0);
            float p1 = ex2f(accs[nf][1] - m0);
            float p2 = ex2f(accs[nf][2] - m1);
            float p3 = ex2f(accs[nf][3] - m1);
            sum0 += p0 + p1;
            sum1 += p2 + p3;
            uint32_t lo = h2_as_u32(__floats2half2_rn(p0, p1));
            uint32_t hi = h2_as_u32(__floats2half2_rn(p2, p3));
            int kc = nf >> 1;
            if ((nf & 1) == 0) { ph[kc][0] = lo; ph[kc][1] = hi; }
            else               { ph[kc][2] = lo; ph[kc][3] = hi; }
        }
        sum0 += __shfl_xor_sync(0xFFFFFFFFu, sum0, 1);
        sum0 += __shfl_xor_sync(0xFFFFFFFFu, sum0, 2);
        sum1 += __shfl_xor_sync(0xFFFFFFFFu, sum1, 1);
        sum1 += __shfl_xor_sync(0xFFFFFFFFu, sum1, 2);
        l0 = l0 * sc0 + sum0;
        l1 = l1 * sc1 + sum1;

        #pragma unroll
        for (int nf = 0; nf < 16; nf++) {
            acc_o[nf][0] *= sc0; acc_o[nf][1] *= sc0;
            acc_o[nf][2] *= sc1; acc_o[nf][3] *= sc1;
        }

        // ---- O += P V, pipelined V-frag loads ----
        #pragma unroll
        for (int kc = 0; kc < 8; kc++) {
            uint32_t vbuf[2][4];
            {
                uint32_t addr = smem_u32(
                    &sV[(kc * 16 + (lane & 15)) * FL_STRIDE + 0 * 16 + ((lane >> 4) << 3)]);
                ldsm_x4_t(vbuf[0][0], vbuf[0][1], vbuf[0][2], vbuf[0][3], addr);
            }
            #pragma unroll
            for (int nf2 = 0; nf2 < 8; nf2++) {
                if (nf2 < 7) {
                    uint32_t addr = smem_u32(
                        &sV[(kc * 16 + (lane & 15)) * FL_STRIDE + (nf2 + 1) * 16 + ((lane >> 4) << 3)]);
                    ldsm_x4_t(vbuf[(nf2 + 1) & 1][0], vbuf[(nf2 + 1) & 1][1],
                              vbuf[(nf2 + 1) & 1][2], vbuf[(nf2 + 1) & 1][3], addr);
                }
                const uint32_t* vb = vbuf[nf2 & 1];
                uint32_t bA[2] = {vb[0], vb[1]}, bB[2] = {vb[2], vb[3]};
                mma16816(acc_o[nf2 * 2],     ph[kc], bA);
                mma16816(acc_o[nf2 * 2 + 1], ph[kc], bB);
            }
        }
        __syncthreads();
    }

    // ---- normalize + write [b, n, h*128+d] ----
    float inv0 = __frcp_rn(l0), inv1 = __frcp_rn(l1);
    int n0 = qt * 128 + w * 16 + g;
    __half* dst0 = g_ao + ((size_t)(b * N_ + n0)) * DIM_ + h * D_;
    __half* dst1 = dst0 + (size_t)8 * DIM_;
    #pragma unroll
    for (int nf = 0; nf < 16; nf++) {
        int col = nf * 8 + cpair;
        *(__half2*)&dst0[col] = __floats2half2_rn(acc_o[nf][0] * inv0, acc_o[nf][1] * inv0);
        *(__half2*)&dst1[col] = __floats2half2_rn(acc_o[nf][2] * inv1, acc_o[nf][3] * inv1);
    }
}

// ---------------- launch (stream fork/join for independent prologue) ----------------
extern "C" void kernel_launch(void* const* d_in, const int* in_sizes, int n_in,
                              void* d_out, int out_size) {
    const float* x        = (const float*)d_in[0];
    const float* ln_g     = (const float*)d_in[1];
    const float* ln_b     = (const float*)d_in[2];
    const float* qkv_w    = (const float*)d_in[3];
    const float* qkv_b    = (const float*)d_in[4];
    const float* proj_w   = (const float*)d_in[5];
    const float* proj_b   = (const float*)d_in[6];
    const float* att_bias = (const float*)d_in[7];
    const int*   bias_idx = (const int*)d_in[8];
    float* out = (float*)d_out;

    int n_off = in_sizes[7] / H_;   // 1024

    static bool inited = false;
    static cudaStream_t s_bias, s_cvt;
    static cudaEvent_t e_fork, e_bias, e_cvt;
    if (!inited) {
        inited = true;
        cudaStreamCreateWithFlags(&s_bias, cudaStreamNonBlocking);
        cudaStreamCreateWithFlags(&s_cvt,  cudaStreamNonBlocking);
        cudaEventCreateWithFlags(&e_fork, cudaEventDisableTiming);
        cudaEventCreateWithFlags(&e_bias, cudaEventDisableTiming);
        cudaEventCreateWithFlags(&e_cvt,  cudaEventDisableTiming);
        cudaFuncSetAttribute(flash_kernel,
                             cudaFuncAttributeMaxDynamicSharedMemorySize, FL_SMEM_BYTES);
        cudaFuncSetAttribute(gemm_f16<EPI_QKV>,
                             cudaFuncAttributeMaxDynamicSharedMemorySize, GEMM_SMEM);
        cudaFuncSetAttribute(gemm_f16<EPI_PROJ>,
                             cudaFuncAttributeMaxDynamicSharedMemorySize, GEMM_SMEM);
    }

    // fork
    cudaEventRecord(e_fork, 0);
    cudaStreamWaitEvent(s_bias, e_fork, 0);
    cudaStreamWaitEvent(s_cvt,  e_fork, 0);

    bias16_kernel<<<dim3(N_ * N_ / 256, H_), 256, 0, s_bias>>>(att_bias, bias_idx, n_off);
    cudaEventRecord(e_bias, s_bias);

    cvt_kernel<<<16384, 256, 0, s_cvt>>>((const float4*)qkv_w, (const float4*)proj_w);
    cudaEventRecord(e_cvt, s_cvt);

    ln_kernel<<<ROWS_, 256>>>(x, ln_g, ln_b);

    cudaStreamWaitEvent(0, e_cvt, 0);
    gemm_f16<EPI_QKV><<<dim3(QKV_OUT_ / 128, ROWS_ / 128), 256, GEMM_SMEM>>>(
        qkv_b, nullptr);

    cudaStreamWaitEvent(0, e_bias, 0);
    flash_kernel<<<dim3(N_ / 128, BH_), 256, FL_SMEM_BYTES>>>();

    gemm_f16<EPI_PROJ><<<dim3(DIM_ / 128, ROWS_ / 128), 256, GEMM_SMEM>>>(
        proj_b, out);
}

// round 16
// speedup vs baseline: 1.1327x; 1.0777x over previous
#include <cuda_runtime.h>
#include <cuda_fp16.h>
#include <cstdint>

#define DEV_INLINE __device__ __forceinline__

// Problem constants
constexpr int B_    = 16;
constexpr int N_    = 1024;
constexpr int H_    = 16;
constexpr int D_    = 128;
constexpr int DIM_  = 2048;
constexpr int QKV_OUT_ = 6144;
constexpr int ROWS_ = B_ * N_;     // 16384
constexpr int BH_   = B_ * H_;     // 256
constexpr float LOG2E_ = 1.4426950408889634f;
constexpr float SCALE_ = 0.08838834764831845f;          // 128^-0.5
constexpr float QSC_   = SCALE_ * LOG2E_;               // q pre-scale, log2 domain
constexpr float LN_EPS_ = 1e-5f;

// ---------------- device scratch (static, no allocs) ----------------
__device__ __align__(16) __half g_xn  [(size_t)ROWS_ * DIM_];
__device__ __align__(16) __half g_wqkv[(size_t)DIM_ * QKV_OUT_];
__device__ __align__(16) __half g_wproj[(size_t)DIM_ * DIM_];
__device__ __align__(16) __half g_q   [(size_t)BH_ * N_ * D_];       // [bh][n][d], pre-scaled*log2e
__device__ __align__(16) __half g_k   [(size_t)BH_ * N_ * D_];       // [bh][n][d]
__device__ __align__(16) __half g_v   [(size_t)BH_ * N_ * D_];       // [bh][n][d]
__device__ __align__(16) __half g_bias16[(size_t)H_ * N_ * N_];      // gathered bias * log2e, fp16
__device__ __align__(16) __half g_ao  [(size_t)ROWS_ * DIM_];        // attn out [b,n,h*D+d]

// ---------------- helpers ----------------
DEV_INLINE uint32_t smem_u32(const void* p) {
    return (uint32_t)__cvta_generic_to_shared(p);
}
DEV_INLINE void cp16(void* s, const void* g) {
    asm volatile("cp.async.cg.shared.global [%0], [%1], 16;\n"
                 :: "r"(smem_u32(s)), "l"(g));
}
DEV_INLINE void cp_commit() { asm volatile("cp.async.commit_group;\n"); }
template <int n>
DEV_INLINE void cp_wait() { asm volatile("cp.async.wait_group %0;\n" :: "n"(n)); }

DEV_INLINE uint32_t h2_as_u32(__half2 h) {
    return *reinterpret_cast<uint32_t*>(&h);
}
DEV_INLINE float ex2f(float x) {
    float y;
    asm("ex2.approx.f32 %0, %1;" : "=f"(y) : "f"(x));
    return y;
}

DEV_INLINE void ldsm_x4(uint32_t& r0, uint32_t& r1, uint32_t& r2, uint32_t& r3, uint32_t a) {
    asm volatile("ldmatrix.sync.aligned.m8n8.x4.shared.b16 {%0,%1,%2,%3}, [%4];"
                 : "=r"(r0), "=r"(r1), "=r"(r2), "=r"(r3) : "r"(a));
}
DEV_INLINE void ldsm_x4_t(uint32_t& r0, uint32_t& r1, uint32_t& r2, uint32_t& r3, uint32_t a) {
    asm volatile("ldmatrix.sync.aligned.m8n8.x4.trans.shared.b16 {%0,%1,%2,%3}, [%4];"
                 : "=r"(r0), "=r"(r1), "=r"(r2), "=r"(r3) : "r"(a));
}
DEV_INLINE void mma16816(float* c, const uint32_t* a, const uint32_t* b) {
    asm volatile(
        "mma.sync.aligned.m16n8k16.row.col.f32.f16.f16.f32 "
        "{%0,%1,%2,%3}, {%4,%5,%6,%7}, {%8,%9}, {%0,%1,%2,%3};"
        : "+f"(c[0]), "+f"(c[1]), "+f"(c[2]), "+f"(c[3])
        : "r"(a[0]), "r"(a[1]), "r"(a[2]), "r"(a[3]), "r"(b[0]), "r"(b[1]));
}

DEV_INLINE float warp_sum(float v) {
    #pragma unroll
    for (int o = 16; o; o >>= 1) v += __shfl_xor_sync(0xFFFFFFFFu, v, o);
    return v;
}
DEV_INLINE float block_sum(float v, float* sred, int tid) {
    int lane = tid & 31, w = tid >> 5;
    v = warp_sum(v);
    if (lane == 0) sred[w] = v;
    __syncthreads();
    float r = sred[0];
    #pragma unroll
    for (int i = 1; i < 8; i++) r += sred[i];
    __syncthreads();
    return r;
}

// ---------------- weight fp32 -> fp16 conversion ----------------
__global__ void cvt_kernel(const float4* __restrict__ qkv_w, const float4* __restrict__ proj_w) {
    int i = blockIdx.x * blockDim.x + threadIdx.x;
    const int n1 = DIM_ * QKV_OUT_ / 4;
    const int n2 = DIM_ * DIM_ / 4;
    if (i < n1) {
        float4 v = qkv_w[i];
        __half2* dst = (__half2*)g_wqkv;
        dst[2 * i]     = __floats2half2_rn(v.x, v.y);
        dst[2 * i + 1] = __floats2half2_rn(v.z, v.w);
    } else if (i < n1 + n2) {
        int j = i - n1;
        float4 v = proj_w[j];
        __half2* dst = (__half2*)g_wproj;
        dst[2 * j]     = __floats2half2_rn(v.x, v.y);
        dst[2 * j + 1] = __floats2half2_rn(v.z, v.w);
    }
}

// ------- gather attention bias (scaled by log2e) to fp16 [h][i][j] -------
__global__ void bias16_kernel(const float* __restrict__ att_bias,
                              const int* __restrict__ idxs, int n_off) {
    int ij = blockIdx.x * 256 + threadIdx.x;
    int h  = blockIdx.y;
    g_bias16[(size_t)h * N_ * N_ + ij] =
        __float2half(att_bias[h * n_off + idxs[ij]] * LOG2E_);
}

// ---------------- LayerNorm ----------------
__global__ void ln_kernel(const float* __restrict__ x,
                          const float* __restrict__ gamma,
                          const float* __restrict__ beta) {
    __shared__ float sred[8];
    int row = blockIdx.x;
    int tid = threadIdx.x;
    const float4* x4 = (const float4*)(x + (size_t)row * DIM_);
    float4 v0 = x4[tid];
    float4 v1 = x4[tid + 256];

    float s = v0.x + v0.y + v0.z + v0.w + v1.x + v1.y + v1.z + v1.w;
    float q = v0.x*v0.x + v0.y*v0.y + v0.z*v0.z + v0.w*v0.w
            + v1.x*v1.x + v1.y*v1.y + v1.z*v1.z + v1.w*v1.w;

    float tot_s = block_sum(s, sred, tid);
    float tot_q = block_sum(q, sred, tid);
    float mean = tot_s * (1.0f / DIM_);
    float var  = tot_q * (1.0f / DIM_) - mean * mean;
    float rstd = rsqrtf(var + LN_EPS_);

    const float4* g4 = (const float4*)gamma;
    const float4* b4 = (const float4*)beta;
    float4 ga = g4[tid], gb = g4[tid + 256];
    float4 ba = b4[tid], bb = b4[tid + 256];

    __half2* o2 = (__half2*)(g_xn + (size_t)row * DIM_);
    o2[2 * tid]       = __floats2half2_rn((v0.x - mean) * rstd * ga.x + ba.x,
                                          (v0.y - mean) * rstd * ga.y + ba.y);
    o2[2 * tid + 1]   = __floats2half2_rn((v0.z - mean) * rstd * ga.z + ba.z,
                                          (v0.w - mean) * rstd * ga.w + ba.w);
    o2[512 + 2 * tid]     = __floats2half2_rn((v1.x - mean) * rstd * gb.x + bb.x,
                                              (v1.y - mean) * rstd * gb.y + bb.y);
    o2[512 + 2 * tid + 1] = __floats2half2_rn((v1.z - mean) * rstd * gb.z + bb.z,
                                              (v1.w - mean) * rstd * gb.w + bb.w);
}

// ------- dense GEMMs: 4 warps, 64x64 warp tile, 4-stage cp.async -------
enum { EPI_QKV = 0, EPI_PROJ = 1 };

constexpr int AS_STAGE_B = 128 * 40 * 2;   // 10240
constexpr int BS_STAGE_B = 32 * 136 * 2;   //  8704
constexpr int AS_TOT_B   = 4 * AS_STAGE_B; // 40960
constexpr int GEMM_SMEM  = AS_TOT_B + 4 * BS_STAGE_B;  // 75776

template <int EPI>
__global__ void __launch_bounds__(128, 2)
gemm_f16(const float* __restrict__ bias, float* __restrict__ outf) {
    constexpr int K   = 2048;
    constexpr int LDA = 2048;
    constexpr int LDB = (EPI == EPI_QKV) ? 6144 : 2048;
    constexpr int NT  = K / 32;   // 64 k-tiles

    extern __shared__ __align__(16) char dynsm[];

    const int bm = blockIdx.y * 128;
    const int bn = blockIdx.x * 128;

    const __half* __restrict__ A  = (EPI == EPI_QKV) ? g_xn : g_ao;
    const __half* __restrict__ Bp = (EPI == EPI_QKV) ? g_wqkv : g_wproj;

    const int tid  = threadIdx.x;
    const int lane = tid & 31;
    const int warp = tid >> 5;   // 0..3
    const int wm = warp & 1;     // 2 warps along M (64 rows each)
    const int wn = warp >> 1;    // 2 warps along N (64 cols each)

    float acc[4][8][4];
    #pragma unroll
    for (int i = 0; i < 4; i++)
        #pragma unroll
        for (int j = 0; j < 8; j++)
            #pragma unroll
            for (int r = 0; r < 4; r++) acc[i][j][r] = 0.0f;

    auto As = [&](int s) -> __half (*)[40] {
        return reinterpret_cast<__half(*)[40]>(dynsm + s * AS_STAGE_B);
    };
    auto Bs = [&](int s) -> __half (*)[136] {
        return reinterpret_cast<__half(*)[136]>(dynsm + AS_TOT_B + s * BS_STAGE_B);
    };

    auto load_tile = [&](int s, int k0) {
        __half (*as)[40]  = As(s);
        __half (*bs)[136] = Bs(s);
        #pragma unroll
        for (int i = 0; i < 4; i++) {              // A: 128 x 32 halves
            int lin = tid + i * 128;
            int m  = lin >> 2;
            int kq = (lin & 3) << 3;
            cp16(&as[m][kq], &A[(size_t)(bm + m) * LDA + k0 + kq]);
        }
        #pragma unroll
        for (int i = 0; i < 4; i++) {              // B: 32 x 128 halves
            int lin = tid + i * 128;
            int kk = lin >> 4;
            int cq = (lin & 15) << 3;
            cp16(&bs[kk][cq], &Bp[(size_t)(k0 + kk) * LDB + bn + cq]);
        }
        cp_commit();
    };

    load_tile(0, 0);
    load_tile(1, 32);
    load_tile(2, 64);

    #pragma unroll 1
    for (int t = 0; t < NT; t++) {
        if (t <= NT - 3)      cp_wait<2>();
        else if (t == NT - 2) cp_wait<1>();
        else                  cp_wait<0>();
        __syncthreads();   // single barrier per iteration

        if (t + 3 < NT) load_tile((t + 3) & 3, (t + 3) * 32);

        const int s = t & 3;
        __half (*as)[40]  = As(s);
        __half (*bs)[136] = Bs(s);
        #pragma unroll
        for (int ks = 0; ks < 2; ks++) {
            uint32_t af[4][4];
            #pragma unroll
            for (int mf = 0; mf < 4; mf++) {
                uint32_t addr = smem_u32(
                    &as[wm * 64 + mf * 16 + (lane & 15)][ks * 16 + ((lane >> 4) << 3)]);
                ldsm_x4(af[mf][0], af[mf][1], af[mf][2], af[mf][3], addr);
            }
            uint32_t bf[8][2];
            #pragma unroll
            for (int np = 0; np < 4; np++) {
                uint32_t addr = smem_u32(
                    &bs[ks * 16 + (lane & 15)][wn * 64 + np * 16 + ((lane >> 4) << 3)]);
                uint32_t r0, r1, r2, r3;
                ldsm_x4_t(r0, r1, r2, r3, addr);
                bf[np * 2][0] = r0;     bf[np * 2][1] = r1;
                bf[np * 2 + 1][0] = r2; bf[np * 2 + 1][1] = r3;
            }
            #pragma unroll
            for (int mf = 0; mf < 4; mf++)
                #pragma unroll
                for (int nf = 0; nf < 8; nf++)
                    mma16816(acc[mf][nf], af[mf], bf[nf]);
        }
    }

    // epilogue
    const int g     = lane >> 2;
    const int cpair = (lane & 3) << 1;
    #pragma unroll
    for (int mf = 0; mf < 4; mf++)
        #pragma unroll
        for (int nf = 0; nf < 8; nf++) {
            int row0 = bm + wm * 64 + mf * 16 + g;
            int col  = bn + wn * 64 + nf * 8 + cpair;
            #pragma unroll
            for (int rr = 0; rr < 2; rr++) {
                int row = row0 + rr * 8;
                float v0 = acc[mf][nf][rr * 2];
                float v1 = acc[mf][nf][rr * 2 + 1];
                if constexpr (EPI == EPI_QKV) {
                    v0 += bias[col];
                    v1 += bias[col + 1];
                    int tsel = col >> 11;
                    int r = col & 2047;
                    int h = r >> 7, d = r & 127;
                    int b = row >> 10, n = row & 1023;
                    int bhi = (b << 4) + h;
                    size_t off = ((size_t)bhi * N_ + n) * D_ + d;
                    if (tsel == 0) {
                        *(__half2*)&g_q[off] = __floats2half2_rn(v0 * QSC_, v1 * QSC_);
                    } else if (tsel == 1) {
                        *(__half2*)&g_k[off] = __floats2half2_rn(v0, v1);
                    } else {
                        *(__half2*)&g_v[off] = __floats2half2_rn(v0, v1);
                    }
                } else {
                    float2 o;
                    o.x = v0 + bias[col];
                    o.y = v1 + bias[col + 1];
                    *(float2*)&outf[(size_t)row * DIM_ + col] = o;
                }
            }
        }
}

// ------- fused flash attention (R15: log2 softmax, bias-seeded accumulators) -------
constexpr int FL_STRIDE = 136;
constexpr int FL_TILE   = 128 * FL_STRIDE;
constexpr int FL_STAGE  = 3 * FL_TILE;               // K + V + bias
constexpr int FL_SMEM_BYTES = 2 * FL_STAGE * 2;      // 208896

__global__ void __launch_bounds__(256, 1)
flash_kernel() {
    extern __shared__ char g_smem[];
    __half* sm = (__half*)g_smem;

    const int tid  = threadIdx.x;
    const int lane = tid & 31;
    const int w    = tid >> 5;
    const int qt   = blockIdx.x;
    const int bh   = blockIdx.y;
    const int h    = bh & 15;
    const int b    = bh >> 4;

    const __half* __restrict__ Qp = g_q + ((size_t)bh * N_ + qt * 128) * D_;
    const __half* __restrict__ Kp = g_k + (size_t)bh * N_ * D_;
    const __half* __restrict__ Vp = g_v + (size_t)bh * N_ * D_;
    const __half* __restrict__ Bb = g_bias16 + (size_t)h * N_ * N_ + (size_t)(qt * 128) * N_;

    {
        __half* sQ = sm;
        #pragma unroll
        for (int i = 0; i < 8; i++) {
            int chunk = tid + i * 256;
            int r  = chunk >> 4;
            int c8 = (chunk & 15) << 3;
            *(float4*)&sQ[r * FL_STRIDE + c8] = *(const float4*)&Qp[r * D_ + c8];
        }
    }
    __syncthreads();
    uint32_t aq[8][4];
    #pragma unroll
    for (int kc = 0; kc < 8; kc++) {
        uint32_t addr = smem_u32(
            &sm[(w * 16 + (lane & 15)) * FL_STRIDE + kc * 16 + ((lane >> 4) << 3)]);
        ldsm_x4(aq[kc][0], aq[kc][1], aq[kc][2], aq[kc][3], addr);
    }
    __syncthreads();

    auto load_kv = [&](int s, int jt) {
        __half* sK = sm + s * FL_STAGE;
        __half* sV = sK + FL_TILE;
        __half* sB = sV + FL_TILE;
        #pragma unroll
        for (int i = 0; i < 8; i++) {
            int chunk = tid + i * 256;
            int r  = chunk >> 4;
            int c8 = (chunk & 15) << 3;
            cp16(&sK[r * FL_STRIDE + c8], &Kp[(size_t)(jt * 128 + r) * D_ + c8]);
        }
        #pragma unroll
        for (int i = 0; i < 8; i++) {
            int chunk = tid + i * 256;
            int r  = chunk >> 4;
            int c8 = (chunk & 15) << 3;
            cp16(&sV[r * FL_STRIDE + c8], &Vp[(size_t)(jt * 128 + r) * D_ + c8]);
        }
        #pragma unroll
        for (int i = 0; i < 8; i++) {
            int chunk = tid + i * 256;
            int r  = chunk >> 4;
            int c8 = (chunk & 15) << 3;
            cp16(&sB[r * FL_STRIDE + c8], &Bb[(size_t)r * N_ + jt * 128 + c8]);
        }
        cp_commit();
    };

    float acc_o[16][4];
    #pragma unroll
    for (int i = 0; i < 16; i++)
        #pragma unroll
        for (int r = 0; r < 4; r++) acc_o[i][r] = 0.0f;
    float m0 = -1e30f, m1 = -1e30f, l0 = 0.0f, l1 = 0.0f;

    const int g = lane >> 2;
    const int cpair = (lane & 3) << 1;

    load_kv(0, 0);

    #pragma unroll 1
    for (int jt = 0; jt < 8; jt++) {
        if (jt + 1 < 8) { load_kv((jt + 1) & 1, jt + 1); cp_wait<1>(); }
        else            { cp_wait<0>(); }
        __syncthreads();

        const __half* sK = sm + (jt & 1) * FL_STAGE;
        const __half* sV = sK + FL_TILE;
        const __half* sB = sV + FL_TILE;

        // ---- seed S accumulators with bias fragments (C init = bias) ----
        const __half* srow0 = sB + (size_t)(w * 16 + g) * FL_STRIDE;
        const __half* srow1 = srow0 + 8 * FL_STRIDE;
        float accs[16][4];
        #pragma unroll
        for (int nf = 0; nf < 16; nf++) {
            int col = nf * 8 + cpair;
            __half2 b0 = *(const __half2*)&srow0[col];
            __half2 b1 = *(const __half2*)&srow1[col];
            accs[nf][0] = __low2float(b0);
            accs[nf][1] = __high2float(b0);
            accs[nf][2] = __low2float(b1);
            accs[nf][3] = __high2float(b1);
        }

        // ---- S = bias + Q K^T, pipelined K-frag loads ----
        #pragma unroll
        for (int kc = 0; kc < 8; kc++) {
            uint32_t kbuf[2][4];
            {
                uint32_t addr = smem_u32(
                    &sK[(0 * 16 + (lane & 15)) * FL_STRIDE + kc * 16 + ((lane >> 4) << 3)]);
                ldsm_x4(kbuf[0][0], kbuf[0][1], kbuf[0][2], kbuf[0][3], addr);
            }
            #pragma unroll
            for (int nf2 = 0; nf2 < 8; nf2++) {
                if (nf2 < 7) {
                    uint32_t addr = smem_u32(
                        &sK[((nf2 + 1) * 16 + (lane & 15)) * FL_STRIDE + kc * 16 + ((lane >> 4) << 3)]);
                    ldsm_x4(kbuf[(nf2 + 1) & 1][0], kbuf[(nf2 + 1) & 1][1],
                            kbuf[(nf2 + 1) & 1][2], kbuf[(nf2 + 1) & 1][3], addr);
                }
                const uint32_t* kb = kbuf[nf2 & 1];
                uint32_t bA[2] = {kb[0], kb[2]}, bB[2] = {kb[1], kb[3]};
                mma16816(accs[nf2 * 2],     aq[kc], bA);
                mma16816(accs[nf2 * 2 + 1], aq[kc], bB);
            }
        }

        // ---- online softmax (base-2), bias already folded in ----
        float mx0 = -1e30f, mx1 = -1e30f;
        #pragma unroll
        for (int nf = 0; nf < 16; nf++) {
            mx0 = fmaxf(mx0, fmaxf(accs[nf][0], accs[nf][1]));
            mx1 = fmaxf(mx1, fmaxf(accs[nf][2], accs[nf][3]));
        }
        mx0 = fmaxf(mx0, __shfl_xor_sync(0xFFFFFFFFu, mx0, 1));
        mx0 = fmaxf(mx0, __shfl_xor_sync(0xFFFFFFFFu, mx0, 2));
        mx1 = fmaxf(mx1, __shfl_xor_sync(0xFFFFFFFFu, mx1, 1));
        mx1 = fmaxf(mx1, __shfl_xor_sync(0xFFFFFFFFu, mx1, 2));

        float mn0 = fmaxf(m0, mx0), mn1 = fmaxf(m1, mx1);
        float sc0 = ex2f(m0 - mn0), sc1 = ex2f(m1 - mn1);
        m0 = mn0; m1 = mn1;

        float sum0 = 0.0f, sum1 = 0.0f;
        uint32_t ph[8][4];
        #pragma unroll
        for (int nf = 0; nf < 16; nf++) {
            float p0 = ex2f(accs[nf][0] - m0);
            float p1 = ex2f(accs[nf][1] - m0);
            float p2 = ex2f(accs[nf][2] - m1);
            float p3 = ex2f(accs[nf][3] - m1);
            sum0 += p0 + p1;
            sum1 += p2 + p3;
            uint32_t lo = h2_as_u32(__floats2half2_rn(p0, p1));
            uint32_t hi = h2_as_u32(__floats2half2_rn(p2, p3));
            int kc = nf >> 1;
            if ((nf & 1) == 0) { ph[kc][0] = lo; ph[kc][1] = hi; }
            else               { ph[kc][2] = lo; ph[kc][3] = hi; }
        }
        sum0 += __shfl_xor_sync(0xFFFFFFFFu, sum0, 1);
        sum0 += __shfl_xor_sync(0xFFFFFFFFu, sum0, 2);
        sum1 += __shfl_xor_sync(0xFFFFFFFFu, sum1, 1);
        sum1 += __shfl_xor_sync(0xFFFFFFFFu, sum1, 2);
        l0 = l0 * sc0 + sum0;
        l1 = l1 * sc1 + sum1;

        #pragma unroll
        for (int nf = 0; nf < 16; nf++) {
            acc_o[nf][0] *= sc0; acc_o[nf][1] *= sc0;
            acc_o[nf][2] *= sc1; acc_o[nf][3] *= sc1;
        }

        // ---- O += P V, pipelined V-frag loads ----
        #pragma unroll
        for (int kc = 0; kc < 8; kc++) {
            uint32_t vbuf[2][4];
            {
                uint32_t addr = smem_u32(
                    &sV[(kc * 16 + (lane & 15)) * FL_STRIDE + 0 * 16 + ((lane >> 4) << 3)]);
                ldsm_x4_t(vbuf[0][0], vbuf[0][1], vbuf[0][2], vbuf[0][3], addr);
            }
            #pragma unroll
            for (int nf2 = 0; nf2 < 8; nf2++) {
                if (nf2 < 7) {
                    uint32_t addr = smem_u32(
                        &sV[(kc * 16 + (lane & 15)) * FL_STRIDE + (nf2 + 1) * 16 + ((lane >> 4) << 3)]);
                    ldsm_x4_t(vbuf[(nf2 + 1) & 1][0], vbuf[(nf2 + 1) & 1][1],
                              vbuf[(nf2 + 1) & 1][2], vbuf[(nf2 + 1) & 1][3], addr);
                }
                const uint32_t* vb = vbuf[nf2 & 1];
                uint32_t bA[2] = {vb[0], vb[1]}, bB[2] = {vb[2], vb[3]};
                mma16816(acc_o[nf2 * 2],     ph[kc], bA);
                mma16816(acc_o[nf2 * 2 + 1], ph[kc], bB);
            }
        }
        __syncthreads();
    }

    // ---- normalize + write [b, n, h*128+d] ----
    float inv0 = __frcp_rn(l0), inv1 = __frcp_rn(l1);
    int n0 = qt * 128 + w * 16 + g;
    __half* dst0 = g_ao + ((size_t)(b * N_ + n0)) * DIM_ + h * D_;
    __half* dst1 = dst0 + (size_t)8 * DIM_;
    #pragma unroll
    for (int nf = 0; nf < 16; nf++) {
        int col = nf * 8 + cpair;
        *(__half2*)&dst0[col] = __floats2half2_rn(acc_o[nf][0] * inv0, acc_o[nf][1] * inv0);
        *(__half2*)&dst1[col] = __floats2half2_rn(acc_o[nf][2] * inv1, acc_o[nf][3] * inv1);
    }
}

// ---------------- launch (stream fork/join for independent prologue) ----------------
extern "C" void kernel_launch(void* const* d_in, const int* in_sizes, int n_in,
                              void* d_out, int out_size) {
    const float* x        = (const float*)d_in[0];
    const float* ln_g     = (const float*)d_in[1];
    const float* ln_b     = (const float*)d_in[2];
    const float* qkv_w    = (const float*)d_in[3];
    const float* qkv_b    = (const float*)d_in[4];
    const float* proj_w   = (const float*)d_in[5];
    const float* proj_b   = (const float*)d_in[6];
    const float* att_bias = (const float*)d_in[7];
    const int*   bias_idx = (const int*)d_in[8];
    float* out = (float*)d_out;

    int n_off = in_sizes[7] / H_;   // 1024

    static bool inited = false;
    static cudaStream_t s_bias, s_cvt;
    static cudaEvent_t e_fork, e_bias, e_cvt;
    if (!inited) {
        inited = true;
        cudaStreamCreateWithFlags(&s_bias, cudaStreamNonBlocking);
        cudaStreamCreateWithFlags(&s_cvt,  cudaStreamNonBlocking);
        cudaEventCreateWithFlags(&e_fork, cudaEventDisableTiming);
        cudaEventCreateWithFlags(&e_bias, cudaEventDisableTiming);
        cudaEventCreateWithFlags(&e_cvt,  cudaEventDisableTiming);
        cudaFuncSetAttribute(flash_kernel,
                             cudaFuncAttributeMaxDynamicSharedMemorySize, FL_SMEM_BYTES);
        cudaFuncSetAttribute(gemm_f16<EPI_QKV>,
                             cudaFuncAttributeMaxDynamicSharedMemorySize, GEMM_SMEM);
        cudaFuncSetAttribute(gemm_f16<EPI_PROJ>,
                             cudaFuncAttributeMaxDynamicSharedMemorySize, GEMM_SMEM);
    }

    // fork
    cudaEventRecord(e_fork, 0);
    cudaStreamWaitEvent(s_bias, e_fork, 0);
    cudaStreamWaitEvent(s_cvt,  e_fork, 0);

    bias16_kernel<<<dim3(N_ * N_ / 256, H_), 256, 0, s_bias>>>(att_bias, bias_idx, n_off);
    cudaEventRecord(e_bias, s_bias);

    cvt_kernel<<<16384, 256, 0, s_cvt>>>((const float4*)qkv_w, (const float4*)proj_w);
    cudaEventRecord(e_cvt, s_cvt);

    ln_kernel<<<ROWS_, 256>>>(x, ln_g, ln_b);

    cudaStreamWaitEvent(0, e_cvt, 0);
    gemm_f16<EPI_QKV><<<dim3(QKV_OUT_ / 128, ROWS_ / 128), 128, GEMM_SMEM>>>(
        qkv_b, nullptr);

    cudaStreamWaitEvent(0, e_bias, 0);
    flash_kernel<<<dim3(N_ / 128, BH_), 256, FL_SMEM_BYTES>>>();

    gemm_f16<EPI_PROJ><<<dim3(DIM_ / 128, ROWS_ / 128), 128, GEMM_SMEM>>>(
        proj_b, out);
}